// round 14
// baseline (speedup 1.0000x reference)
#include <cuda_runtime.h>
#include <cuda_bf16.h>
#include <math.h>

#define Bn 256
#define Tn 250
#define Zn 128
#define Hn 256
#define Dn 512
#define Kn 20
#define Pn 123
#define TB (Tn*Bn)

typedef unsigned long long ull;
typedef unsigned int u32;
typedef unsigned short u16;

__device__ u32  g_hfH[2][Bn*Hn/2];
__device__ u32  g_hfL[2][Bn*Hn/2];
__device__ u32  g_hbH[2][Bn*Hn/2];
__device__ u32  g_hbL[2][Bn*Hn/2];
__device__ u32  g_hdH[2][Bn*Dn/2];
__device__ u32  g_hdL[2][Bn*Dn/2];
__device__ u32  g_hsH[(size_t)TB*(Dn/2)];
__device__ u32  g_hsL[(size_t)TB*(Dn/2)];
__device__ float g_z  [Bn*Zn];
__device__ float g_zgT[4*Dn*Bn];
__device__ float g_cdT[Dn*Bn];
__device__ int   g_pflag[256];
__device__ int   g_done[16];

// ---- fast transcendentals ----
__device__ __forceinline__ float ex2a(float x){ float y; asm("ex2.approx.f32 %0,%1;":"=f"(y):"f"(x)); return y; }
__device__ __forceinline__ float rcpa(float x){ float y; asm("rcp.approx.f32 %0,%1;":"=f"(y):"f"(x)); return y; }
__device__ __forceinline__ float sigf(float x){ return rcpa(1.0f + ex2a(-1.4426950408889634f * x)); }
__device__ __forceinline__ float tanha(float x){ return 1.0f - 2.0f * rcpa(ex2a(2.8853900817779268f * x) + 1.0f); }

__device__ __forceinline__ void ffma2(ull& d, ull a, ull b) {
    asm("fma.rn.f32x2 %0, %1, %2, %0;" : "+l"(d) : "l"(a), "l"(b));
}
__device__ __forceinline__ ull dup2(float w) {
    ull r; u32 u = __float_as_uint(w);
    asm("mov.b64 %0, {%1, %1};" : "=l"(r) : "r"(u));
    return r;
}
__device__ __forceinline__ float2 unpk(ull v) {
    float2 f; asm("mov.b64 {%0, %1}, %2;" : "=f"(f.x), "=f"(f.y) : "l"(v));
    return f;
}
__device__ __forceinline__ int ld_acq(const int* p) {
    int v; asm volatile("ld.acquire.gpu.global.s32 %0, [%1];" : "=r"(v) : "l"(p) : "memory");
    return v;
}
__device__ __forceinline__ void red_rel(int* p) {
    asm volatile("red.release.gpu.global.add.s32 [%0], 1;" :: "l"(p) : "memory");
}
// lanes 0..3 poll the 4 producer flags of one chunk
__device__ __forceinline__ void wait4(const int* flags, int t) {
    int lane = threadIdx.x & 31;
    if (lane < 4) { while (ld_acq(flags + lane) < t) { } }
    __syncwarp();
}
__device__ __forceinline__ u32 pack_hi(float a, float b, u32& lo) {
    __nv_bfloat16 ha = __float2bfloat16_rn(a), hb = __float2bfloat16_rn(b);
    __nv_bfloat16 la = __float2bfloat16_rn(a - __bfloat162float(ha));
    __nv_bfloat16 lb = __float2bfloat16_rn(b - __bfloat162float(hb));
    __nv_bfloat162 ph(ha, hb), pl(la, lb);
    lo = *(u32*)&pl;
    return *(u32*)&ph;
}
__device__ __forceinline__ void mma16(float* c, u32 a0, u32 a1, u32 a2, u32 a3,
                                      u32 b0, u32 b1) {
    asm("mma.sync.aligned.m16n8k16.row.col.f32.bf16.bf16.f32 "
        "{%0,%1,%2,%3}, {%4,%5,%6,%7}, {%8,%9}, {%0,%1,%2,%3};"
        : "+f"(c[0]), "+f"(c[1]), "+f"(c[2]), "+f"(c[3])
        : "r"(a0), "r"(a1), "r"(a2), "r"(a3), "r"(b0), "r"(b1));
}

#define WP 72
#define AP 36

// Pair-local staging + named pair barriers + PER-TERM accumulator chains
// (3 independent chains per nb cell -> chain depth /3) + per-chunk flag waits
// (chunk c needs only producers 4c..4c+3; wait overlaps chunk c-1 MMA).
template<int CN>
__device__ __forceinline__ void mma_steps3(
    float (&accT)[3][4][4], const u32* rh, const u32* rl,
    u32* Ab, const u32* Whi, const u32* Wlo, const int* fbase, int t,
    int srow, int sw, int ra0, int ra1, int n0, int g, int t4)
{
    const int bid = 1 + ((threadIdx.x >> 5) & 3);
    uint4 ph0, ph1, pl0, pl1;
    wait4(fbase, t);
    ph0 = __ldcg((const uint4*)&rh[sw * 4]);  ph1 = __ldcg((const uint4*)&rh[sw * 4 + 16]);
    pl0 = __ldcg((const uint4*)&rl[sw * 4]);  pl1 = __ldcg((const uint4*)&rl[sw * 4 + 16]);
    #pragma unroll 1
    for (int c = 0; c < CN; c++) {
        u32* Ah = Ab + (c & 1) * 2304;
        u32* Al = Ab + 4608 + (c & 1) * 2304;
        *(uint4*)&Ah[srow * AP + sw * 4]      = ph0;
        *(uint4*)&Ah[srow * AP + sw * 4 + 16] = ph1;
        *(uint4*)&Al[srow * AP + sw * 4]      = pl0;
        *(uint4*)&Al[srow * AP + sw * 4 + 16] = pl1;
        if (c < CN - 1) {
            wait4(fbase + 4 * (c + 1), t);
            ph0 = __ldcg((const uint4*)&rh[(c + 1) * 32 + sw * 4]);
            ph1 = __ldcg((const uint4*)&rh[(c + 1) * 32 + sw * 4 + 16]);
            pl0 = __ldcg((const uint4*)&rl[(c + 1) * 32 + sw * 4]);
            pl1 = __ldcg((const uint4*)&rl[(c + 1) * 32 + sw * 4 + 16]);
        }
        asm volatile("bar.sync %0, 64;" :: "r"(bid) : "memory");
        #pragma unroll
        for (int s = 0; s < 4; s++) {
            int o = 8 * s;
            u32 ah0 = Ah[ra0 + o], ah1 = Ah[ra1 + o], ah2 = Ah[ra0 + o + 4], ah3 = Ah[ra1 + o + 4];
            u32 al0 = Al[ra0 + o], al1 = Al[ra1 + o], al2 = Al[ra0 + o + 4], al3 = Al[ra1 + o + 4];
            const u32* bh = Whi + (c * 32 + o + t4) * WP + n0 + g;
            const u32* bl = Wlo + (c * 32 + o + t4) * WP + n0 + g;
            #pragma unroll
            for (int nb = 0; nb < 4; nb++) {
                u32 b0h = bh[8 * nb], b1h = bh[8 * nb + 4 * WP];
                u32 b0l = bl[8 * nb], b1l = bl[8 * nb + 4 * WP];
                mma16(accT[0][nb], ah0, ah1, ah2, ah3, b0h, b1h);
                mma16(accT[1][nb], ah0, ah1, ah2, ah3, b0l, b1l);
                mma16(accT[2][nb], al0, al1, al2, al3, b0h, b1h);
            }
        }
    }
}

// gather the 4 gates of a unit into one lane (cols packed unit*4+gate)
__device__ __forceinline__ float4 gather_gates(const float* a4, int rowSel) {
    float sx = rowSel ? a4[0] : a4[2];
    float sy = rowSel ? a4[1] : a4[3];
    float rx = __shfl_xor_sync(0xffffffffu, sx, 1);
    float ry = __shfl_xor_sync(0xffffffffu, sy, 1);
    return rowSel ? make_float4(rx, ry, a4[2], a4[3])
                  : make_float4(a4[0], a4[1], rx, ry);
}

// =================== persistent encoder =====================================
#define ENC_SMEM 122880
__global__ __launch_bounds__(256) void enc_persist(
    const float* __restrict__ data,
    const float* __restrict__ Wx_f, const float* __restrict__ Wh_f, const float* __restrict__ b_f,
    const float* __restrict__ Wx_b, const float* __restrict__ Wh_b, const float* __restrict__ b_b)
{
    extern __shared__ u32 sm[];
    u32*  Whi = sm;
    u32*  Wlo = sm + 9216;
    u32*  Ab  = sm + 18432;
    float* Wxs = (float*)(sm + 27648);
    float* Xsm = (float*)(sm + 27968);

    const int tid = threadIdx.x, lane = tid & 31, warp = tid >> 5;
    const int g = lane >> 2, t4 = lane & 3;
    const int m0 = (warp & 3) * 16, n0 = (warp >> 2) * 32;
    const int dir = blockIdx.x >> 6, bt = (blockIdx.x >> 4) & 3, ut = blockIdx.x & 15;
    const int b0 = bt * 64, u0 = ut * 16;

    const float* __restrict__ Wh = dir ? Wh_b : Wh_f;
    const float* __restrict__ Wx = dir ? Wx_b : Wx_f;
    const float* __restrict__ bb = dir ? b_b  : b_f;
    u32* hH[2] = { dir ? g_hbH[0] : g_hfH[0], dir ? g_hbH[1] : g_hfH[1] };
    u32* hL[2] = { dir ? g_hbL[0] : g_hfL[0], dir ? g_hbL[1] : g_hfL[1] };
    int* fbase  = g_pflag + (dir * 4 + bt) * 16;
    int* done   = &g_done[dir * 4 + bt];

    for (int i = tid; i < 8192; i += 256) {
        int kp = i >> 6, c = i & 63, ul = c >> 2, gate = c & 3;
        float w0 = __ldg(&Wh[(2 * kp)     * 1024 + gate * Hn + u0 + ul]);
        float w1 = __ldg(&Wh[(2 * kp + 1) * 1024 + gate * Hn + u0 + ul]);
        u32 lo, hi = pack_hi(w0, w1, lo);
        Whi[kp * WP + c] = hi; Wlo[kp * WP + c] = lo;
    }
    for (int i = tid; i < 320; i += 256) {
        int j = i >> 6, c = i & 63, ul = c >> 2, gate = c & 3;
        Wxs[i] = __ldg(&Wx[j * 1024 + gate * Hn + u0 + ul]);
    }

    const int rowSel = t4 & 1;
    const int upart  = t4 >> 1;
    const int myrow  = m0 + g + 8 * rowSel;
    const int nhalf  = n0 >> 5;
    const int srow = ((warp & 3) << 4) + ((warp >> 2) << 3) + (lane >> 2);
    const int sw = lane & 3;
    const int ra0 = (m0 + g) * AP + t4, ra1 = (m0 + g + 8) * AP + t4;

    float4 bsv[4];
    #pragma unroll
    for (int nb = 0; nb < 4; nb++) {
        int u = u0 + 8 * nhalf + 2 * nb + upart;
        bsv[nb] = make_float4(__ldg(&bb[u]), __ldg(&bb[Hn + u]),
                              __ldg(&bb[2 * Hn + u]), __ldg(&bb[3 * Hn + u]));
    }
    float creg[4] = {0, 0, 0, 0};

    if (tid < 64) {
        int xtime = dir ? Tn : 1;
        #pragma unroll
        for (int j = 0; j < 5; j++)
            Xsm[tid * 5 + j] = __ldg(&data[(size_t)(b0 + tid) * 1255 + xtime * 5 + j]);
    }
    __syncthreads();

    for (int t = 0; t < Tn; t++) {
        const u32* hiIn = hH[t & 1]; const u32* loIn = hL[t & 1];
        u32* hiOut = hH[(t + 1) & 1]; u32* loOut = hL[(t + 1) & 1];

        float accT[3][4][4] = {};
        if (t > 0)
            mma_steps3<4>(accT, &hiIn[(size_t)(b0 + srow) * 128], &loIn[(size_t)(b0 + srow) * 128],
                          Ab, Whi, Wlo, fbase, t, srow, sw, ra0, ra1, n0, g, t4);

        const float* xr = &Xsm[(t & 1) * 320 + myrow * 5];
        float x0 = xr[0], x1 = xr[1], x2 = xr[2], x3 = xr[3], x4 = xr[4];
        u32 hiw[4], low[4];
        #pragma unroll
        for (int nb = 0; nb < 4; nb++) {
            float a4[4];
            #pragma unroll
            for (int i = 0; i < 4; i++)
                a4[i] = accT[0][nb][i] + accT[1][nb][i] + accT[2][nb][i];
            float4 p = gather_gates(a4, rowSel);
            int uc = 8 * nhalf + 2 * nb + upart;
            p.x += bsv[nb].x; p.y += bsv[nb].y; p.z += bsv[nb].z; p.w += bsv[nb].w;
            const float* wx = &Wxs[4 * uc];
            p.x = fmaf(x0, wx[0], p.x); p.y = fmaf(x0, wx[1], p.y);
            p.z = fmaf(x0, wx[2], p.z); p.w = fmaf(x0, wx[3], p.w);
            p.x = fmaf(x1, wx[64], p.x); p.y = fmaf(x1, wx[65], p.y);
            p.z = fmaf(x1, wx[66], p.z); p.w = fmaf(x1, wx[67], p.w);
            p.x = fmaf(x2, wx[128], p.x); p.y = fmaf(x2, wx[129], p.y);
            p.z = fmaf(x2, wx[130], p.z); p.w = fmaf(x2, wx[131], p.w);
            p.x = fmaf(x3, wx[192], p.x); p.y = fmaf(x3, wx[193], p.y);
            p.z = fmaf(x3, wx[194], p.z); p.w = fmaf(x3, wx[195], p.w);
            p.x = fmaf(x4, wx[256], p.x); p.y = fmaf(x4, wx[257], p.y);
            p.z = fmaf(x4, wx[258], p.z); p.w = fmaf(x4, wx[259], p.w);
            float cn = sigf(p.y) * creg[nb] + sigf(p.x) * tanha(p.z);
            float h = sigf(p.w) * tanha(cn);
            creg[nb] = cn;
            __nv_bfloat16 hb = __float2bfloat16_rn(h);
            __nv_bfloat16 lb = __float2bfloat16_rn(h - __bfloat162float(hb));
            u32 hl = (u32)*(u16*)&hb | ((u32)*(u16*)&lb << 16);
            u32 pr = __shfl_xor_sync(0xffffffffu, hl, 2);
            hiw[nb] = (hl & 0xFFFFu) | ((pr & 0xFFFFu) << 16);
            low[nb] = (hl >> 16) | (pr & 0xFFFF0000u);
        }
        if (upart == 0) {
            size_t base = (size_t)(b0 + myrow) * 128 + ut * 8 + 4 * nhalf;
            __stcg((uint4*)&hiOut[base], make_uint4(hiw[0], hiw[1], hiw[2], hiw[3]));
            __stcg((uint4*)&loOut[base], make_uint4(low[0], low[1], low[2], low[3]));
        }
        if (tid < 64 && t + 1 < Tn) {
            int xtime = dir ? (Tn - t - 1) : (t + 2);
            #pragma unroll
            for (int j = 0; j < 5; j++)
                Xsm[((t + 1) & 1) * 320 + tid * 5 + j] =
                    __ldg(&data[(size_t)(b0 + tid) * 1255 + xtime * 5 + j]);
        }
        __syncthreads();
        if (tid == 0 && t < Tn - 1) red_rel(fbase + ut);
    }
    if (tid == 0) {
        int old = atomicAdd(done, 1);
        if (old == 15) {
            for (int j = 0; j < 16; j++) atomicExch(fbase + j, 0);
            atomicExch(done, 0);
        }
    }
}

// =================== persistent decoder =====================================
#define DEC_SMEM 188160
__global__ __launch_bounds__(256) void dec_persist(
    const float* __restrict__ data,
    const float* __restrict__ dec_Wx, const float* __restrict__ Wh)
{
    extern __shared__ u32 sm[];
    u32*  Whi = sm;
    u32*  Wlo = sm + 18432;
    u32*  Ab  = sm + 36864;
    float* Wxs = (float*)(sm + 46080);
    float* Xsm = (float*)(sm + 46400);

    const int tid = threadIdx.x, lane = tid & 31, warp = tid >> 5;
    const int g = lane >> 2, t4 = lane & 3;
    const int m0 = (warp & 3) * 16, n0 = (warp >> 2) * 32;
    const int bt = blockIdx.x >> 5, ut = blockIdx.x & 31;
    const int b0 = bt * 64, u0 = ut * 16;
    int* fbase = g_pflag + 128 + bt * 32;
    int* done  = &g_done[8 + bt];

    for (int i = tid; i < 16384; i += 256) {
        int kp = i >> 6, c = i & 63, ul = c >> 2, gate = c & 3;
        float w0 = __ldg(&Wh[(2 * kp)     * 2048 + gate * Dn + u0 + ul]);
        float w1 = __ldg(&Wh[(2 * kp + 1) * 2048 + gate * Dn + u0 + ul]);
        u32 lo, hi = pack_hi(w0, w1, lo);
        Whi[kp * WP + c] = hi; Wlo[kp * WP + c] = lo;
    }
    for (int i = tid; i < 320; i += 256) {
        int j = i >> 6, c = i & 63, ul = c >> 2, gate = c & 3;
        Wxs[i] = __ldg(&dec_Wx[j * 2048 + gate * Dn + u0 + ul]);
    }

    const int rowSel = t4 & 1;
    const int upart  = t4 >> 1;
    const int myrow  = m0 + g + 8 * rowSel;
    const int nhalf  = n0 >> 5;
    const int srow = ((warp & 3) << 4) + ((warp >> 2) << 3) + (lane >> 2);
    const int sw = lane & 3;
    const int ra0 = (m0 + g) * AP + t4, ra1 = (m0 + g + 8) * AP + t4;

    float4 zgv[4]; float creg[4];
    #pragma unroll
    for (int nb = 0; nb < 4; nb++) {
        int u = u0 + 8 * nhalf + 2 * nb + upart;
        int b = b0 + myrow;
        zgv[nb] = make_float4(g_zgT[((size_t)0 * Dn + u) * Bn + b],
                              g_zgT[((size_t)1 * Dn + u) * Bn + b],
                              g_zgT[((size_t)2 * Dn + u) * Bn + b],
                              g_zgT[((size_t)3 * Dn + u) * Bn + b]);
        creg[nb] = g_cdT[(size_t)u * Bn + b];
    }

    if (tid < 64) {
        #pragma unroll
        for (int j = 0; j < 5; j++)
            Xsm[tid * 5 + j] = __ldg(&data[(size_t)(b0 + tid) * 1255 + 0 * 5 + j]);
    }
    __syncthreads();

    for (int t = 0; t < Tn; t++) {
        const u32* hiIn = g_hdH[t & 1]; const u32* loIn = g_hdL[t & 1];
        u32* hiOut = g_hdH[(t + 1) & 1]; u32* loOut = g_hdL[(t + 1) & 1];

        float accT[3][4][4] = {};
        mma_steps3<8>(accT, &hiIn[(size_t)(b0 + srow) * 256], &loIn[(size_t)(b0 + srow) * 256],
                      Ab, Whi, Wlo, fbase, t, srow, sw, ra0, ra1, n0, g, t4);

        const float* xr = &Xsm[(t & 1) * 320 + myrow * 5];
        float x0 = xr[0], x1 = xr[1], x2 = xr[2], x3 = xr[3], x4 = xr[4];
        u32 hiw[4], low[4];
        #pragma unroll
        for (int nb = 0; nb < 4; nb++) {
            float a4[4];
            #pragma unroll
            for (int i = 0; i < 4; i++)
                a4[i] = accT[0][nb][i] + accT[1][nb][i] + accT[2][nb][i];
            float4 p = gather_gates(a4, rowSel);
            int uc = 8 * nhalf + 2 * nb + upart;
            p.x += zgv[nb].x; p.y += zgv[nb].y; p.z += zgv[nb].z; p.w += zgv[nb].w;
            const float* wx = &Wxs[4 * uc];
            p.x = fmaf(x0, wx[0], p.x); p.y = fmaf(x0, wx[1], p.y);
            p.z = fmaf(x0, wx[2], p.z); p.w = fmaf(x0, wx[3], p.w);
            p.x = fmaf(x1, wx[64], p.x); p.y = fmaf(x1, wx[65], p.y);
            p.z = fmaf(x1, wx[66], p.z); p.w = fmaf(x1, wx[67], p.w);
            p.x = fmaf(x2, wx[128], p.x); p.y = fmaf(x2, wx[129], p.y);
            p.z = fmaf(x2, wx[130], p.z); p.w = fmaf(x2, wx[131], p.w);
            p.x = fmaf(x3, wx[192], p.x); p.y = fmaf(x3, wx[193], p.y);
            p.z = fmaf(x3, wx[194], p.z); p.w = fmaf(x3, wx[195], p.w);
            p.x = fmaf(x4, wx[256], p.x); p.y = fmaf(x4, wx[257], p.y);
            p.z = fmaf(x4, wx[258], p.z); p.w = fmaf(x4, wx[259], p.w);
            float cn = sigf(p.y) * creg[nb] + sigf(p.x) * tanha(p.z);
            float h = sigf(p.w) * tanha(cn);
            creg[nb] = cn;
            __nv_bfloat16 hb = __float2bfloat16_rn(h);
            __nv_bfloat16 lb = __float2bfloat16_rn(h - __bfloat162float(hb));
            u32 hl = (u32)*(u16*)&hb | ((u32)*(u16*)&lb << 16);
            u32 pr = __shfl_xor_sync(0xffffffffu, hl, 2);
            hiw[nb] = (hl & 0xFFFFu) | ((pr & 0xFFFFu) << 16);
            low[nb] = (hl >> 16) | (pr & 0xFFFF0000u);
        }
        if (upart == 0) {
            size_t base = (size_t)(b0 + myrow) * 256 + ut * 8 + 4 * nhalf;
            uint4 hv = make_uint4(hiw[0], hiw[1], hiw[2], hiw[3]);
            uint4 lv = make_uint4(low[0], low[1], low[2], low[3]);
            __stcg((uint4*)&hiOut[base], hv);
            __stcg((uint4*)&loOut[base], lv);
            size_t hb2 = ((size_t)t * Bn + b0 + myrow) * 256 + ut * 8 + 4 * nhalf;
            __stcg((uint4*)&g_hsH[hb2], hv);
            __stcg((uint4*)&g_hsL[hb2], lv);
        }
        if (tid < 64 && t + 1 < Tn) {
            #pragma unroll
            for (int j = 0; j < 5; j++)
                Xsm[((t + 1) & 1) * 320 + tid * 5 + j] =
                    __ldg(&data[(size_t)(b0 + tid) * 1255 + (t + 1) * 5 + j]);
        }
        __syncthreads();
        if (tid == 0 && t < Tn - 1) red_rel(fbase + ut);
    }
    if (tid == 0) {
        int old = atomicAdd(done, 1);
        if (old == 31) {
            for (int j = 0; j < 32; j++) atomicExch(fbase + j, 0);
            atomicExch(done, 0);
        }
    }
}

// =================== latent stages ==========================================
__global__ void latent1(const float* __restrict__ W, const float* __restrict__ bias,
                        const float* __restrict__ eps,
                        float* __restrict__ zm, float* __restrict__ zl)
{
    int b = blockIdx.x, j = threadIdx.x;
    const __nv_bfloat16* fh = (const __nv_bfloat16*)g_hfH[0];
    const __nv_bfloat16* fl = (const __nv_bfloat16*)g_hfL[0];
    const __nv_bfloat16* bh = (const __nv_bfloat16*)g_hbH[0];
    const __nv_bfloat16* bl = (const __nv_bfloat16*)g_hbL[0];
    float sm = bias[j], sl = bias[j + Zn];
    for (int k = 0; k < Hn; k++) {
        float a = __bfloat162float(fh[b * Hn + k]) + __bfloat162float(fl[b * Hn + k]);
        sm = fmaf(a, W[k * (2 * Zn) + j], sm);
        sl = fmaf(a, W[k * (2 * Zn) + Zn + j], sl);
    }
    for (int k = 0; k < Hn; k++) {
        float a = __bfloat162float(bh[b * Hn + k]) + __bfloat162float(bl[b * Hn + k]);
        sm = fmaf(a, W[(Hn + k) * (2 * Zn) + j], sm);
        sl = fmaf(a, W[(Hn + k) * (2 * Zn) + Zn + j], sl);
    }
    zm[b * Zn + j] = sm;
    zl[b * Zn + j] = sl;
    g_z[b * Zn + j] = sm + expf(0.5f * sl) * eps[b * Zn + j];
}

__global__ __launch_bounds__(256) void latent2(
    const float* __restrict__ init_W, const float* __restrict__ init_b,
    const float* __restrict__ dec_Wx, const float* __restrict__ dec_b)
{
    __shared__ float zs[32][Zn];
    const int tid = threadIdx.x;
    const int tx = tid & 31, ty = tid >> 5;
    const int b0 = blockIdx.x * 32;
    const int col0 = blockIdx.y * 128;
    const bool isInit = (col0 < 2 * Dn);

    for (int i = tid; i < 32 * Zn; i += 256)
        zs[i >> 7][i & 127] = g_z[(b0 + (i >> 7)) * Zn + (i & 127)];
    __syncthreads();

    const int col = col0 + tx * 4;
    const float* Wcol = isInit ? (init_W + col) : (dec_Wx + 5 * (4 * Dn) + (col - 2 * Dn));
    const int wstride = isInit ? (2 * Dn) : (4 * Dn);

    float acc[4][4] = {};
    #pragma unroll 4
    for (int k = 0; k < Zn; k++) {
        float4 w = *(const float4*)&Wcol[k * wstride];
        float a0 = zs[ty * 4 + 0][k], a1 = zs[ty * 4 + 1][k];
        float a2 = zs[ty * 4 + 2][k], a3 = zs[ty * 4 + 3][k];
        acc[0][0] = fmaf(a0, w.x, acc[0][0]); acc[0][1] = fmaf(a0, w.y, acc[0][1]);
        acc[0][2] = fmaf(a0, w.z, acc[0][2]); acc[0][3] = fmaf(a0, w.w, acc[0][3]);
        acc[1][0] = fmaf(a1, w.x, acc[1][0]); acc[1][1] = fmaf(a1, w.y, acc[1][1]);
        acc[1][2] = fmaf(a1, w.z, acc[1][2]); acc[1][3] = fmaf(a1, w.w, acc[1][3]);
        acc[2][0] = fmaf(a2, w.x, acc[2][0]); acc[2][1] = fmaf(a2, w.y, acc[2][1]);
        acc[2][2] = fmaf(a2, w.z, acc[2][2]); acc[2][3] = fmaf(a2, w.w, acc[2][3]);
        acc[3][0] = fmaf(a3, w.x, acc[3][0]); acc[3][1] = fmaf(a3, w.y, acc[3][1]);
        acc[3][2] = fmaf(a3, w.z, acc[3][2]); acc[3][3] = fmaf(a3, w.w, acc[3][3]);
    }

    __nv_bfloat16* hH = (__nv_bfloat16*)g_hdH[0];
    __nv_bfloat16* hL = (__nv_bfloat16*)g_hdL[0];
    #pragma unroll
    for (int r = 0; r < 4; r++) {
        int b = b0 + ty * 4 + r;
        #pragma unroll
        for (int c = 0; c < 4; c++) {
            int cc = col + c;
            if (isInit) {
                float v = tanhf(acc[r][c] + init_b[cc]);
                if (cc < Dn) {
                    __nv_bfloat16 hb = __float2bfloat16_rn(v);
                    hH[(size_t)b * Dn + cc] = hb;
                    hL[(size_t)b * Dn + cc] = __float2bfloat16_rn(v - __bfloat162float(hb));
                } else {
                    g_cdT[(size_t)(cc - Dn) * Bn + b] = v;
                }
            } else {
                int c2 = cc - 2 * Dn;
                g_zgT[(size_t)c2 * Bn + b] = acc[r][c] + dec_b[c2];
            }
        }
    }
}

// =================== output head ============================================
__global__ __launch_bounds__(256) void mix_kernel(
    const float* __restrict__ Wm, const float* __restrict__ bm, float* __restrict__ out)
{
    __shared__ __align__(16) float As[32][34];
    __shared__ __align__(16) float Ws[32][128];
    __shared__ float ys[32 * 129];
    const int tid = threadIdx.x;
    const int tx = tid & 31, ty = tid >> 5;
    const int row0 = blockIdx.x * 32;
    ull acc[2][4] = {};

    for (int k0 = 0; k0 < Dn; k0 += 32) {
        __syncthreads();
        #pragma unroll
        for (int it = 0; it < 2; it++) {
            int idx = tid + it * 256;
            int r = idx >> 4, j = idx & 15;
            u32 hi = g_hsH[(size_t)(row0 + r) * 256 + (k0 >> 1) + j];
            u32 lo = g_hsL[(size_t)(row0 + r) * 256 + (k0 >> 1) + j];
            __nv_bfloat162 h2 = *(__nv_bfloat162*)&hi;
            __nv_bfloat162 l2 = *(__nv_bfloat162*)&lo;
            As[2 * j][r]     = __bfloat162float(h2.x) + __bfloat162float(l2.x);
            As[2 * j + 1][r] = __bfloat162float(h2.y) + __bfloat162float(l2.y);
        }
        for (int i = tid; i < 32 * 128; i += 256) {
            int k = i >> 7, c = i & 127;
            Ws[k][c] = (c < Pn) ? Wm[(k0 + k) * Pn + c] : 0.f;
        }
        __syncthreads();
        #pragma unroll 4
        for (int k = 0; k < 32; k++) {
            ull a01 = *(const ull*)&As[k][ty * 4];
            ull a23 = *(const ull*)&As[k][ty * 4 + 2];
            float4 w = *(const float4*)&Ws[k][tx * 4];
            ull w0 = dup2(w.x), w1 = dup2(w.y), w2 = dup2(w.z), w3 = dup2(w.w);
            ffma2(acc[0][0], a01, w0); ffma2(acc[0][1], a01, w1);
            ffma2(acc[0][2], a01, w2); ffma2(acc[0][3], a01, w3);
            ffma2(acc[1][0], a23, w0); ffma2(acc[1][1], a23, w1);
            ffma2(acc[1][2], a23, w2); ffma2(acc[1][3], a23, w3);
        }
    }

    #pragma unroll
    for (int pr = 0; pr < 2; pr++)
        #pragma unroll
        for (int c = 0; c < 4; c++) {
            float2 v = unpk(acc[pr][c]);
            int cc = tx * 4 + c;
            float bias = (cc < Pn) ? bm[cc] : 0.f;
            ys[(ty * 4 + pr * 2 + 0) * 129 + cc] = v.x + bias;
            ys[(ty * 4 + pr * 2 + 1) * 129 + cc] = v.y + bias;
        }
    __syncthreads();

    if (tid < 32) {
        int row = row0 + tid;
        int tt = row >> 8, bb2 = row & 255;
        float* o = out + ((size_t)bb2 * Tn + tt) * Pn;
        const float* y = &ys[tid * 129];
        float m = y[0];
        #pragma unroll
        for (int j = 1; j < Kn; j++) m = fmaxf(m, y[j]);
        float e[Kn]; float sum = 0.f;
        #pragma unroll
        for (int j = 0; j < Kn; j++) { e[j] = expf(y[j] - m); sum += e[j]; }
        float inv = 1.f / sum;
        #pragma unroll
        for (int j = 0; j < Kn; j++) o[j] = e[j] * inv;
        #pragma unroll
        for (int j = Kn; j < 3 * Kn; j++) o[j] = y[j];
        #pragma unroll
        for (int j = 3 * Kn; j < 5 * Kn; j++) o[j] = expf(y[j]);
        #pragma unroll
        for (int j = 5 * Kn; j < 6 * Kn; j++) o[j] = tanhf(y[j]);
        o[120] = y[120]; o[121] = y[121]; o[122] = y[122];
    }
}

// =================== launcher ================================================
extern "C" void kernel_launch(void* const* d_in, const int* in_sizes, int n_in,
                              void* d_out, int out_size)
{
    (void)in_sizes; (void)n_in; (void)out_size;
    const float* data      = (const float*)d_in[0];
    const float* eps       = (const float*)d_in[1];
    const float* enc_Wx_f  = (const float*)d_in[2];
    const float* enc_Wh_f  = (const float*)d_in[3];
    const float* enc_b_f   = (const float*)d_in[4];
    const float* enc_Wx_b  = (const float*)d_in[5];
    const float* enc_Wh_b  = (const float*)d_in[6];
    const float* enc_b_b   = (const float*)d_in[7];
    const float* enc_out_W = (const float*)d_in[8];
    const float* enc_out_b = (const float*)d_in[9];
    const float* init_W    = (const float*)d_in[10];
    const float* init_b    = (const float*)d_in[11];
    const float* dec_Wx    = (const float*)d_in[12];
    const float* dec_Wh    = (const float*)d_in[13];
    const float* dec_b     = (const float*)d_in[14];
    const float* mix_W     = (const float*)d_in[15];
    const float* mix_b     = (const float*)d_in[16];
    float* out = (float*)d_out;

    cudaFuncSetAttribute(enc_persist, cudaFuncAttributeMaxDynamicSharedMemorySize, ENC_SMEM);
    cudaFuncSetAttribute(dec_persist, cudaFuncAttributeMaxDynamicSharedMemorySize, DEC_SMEM);

    const size_t params_sz = (size_t)Bn * Tn * Pn;

    enc_persist<<<128, 256, ENC_SMEM>>>(data, enc_Wx_f, enc_Wh_f, enc_b_f,
                                        enc_Wx_b, enc_Wh_b, enc_b_b);
    latent1<<<Bn, 128>>>(enc_out_W, enc_out_b, eps,
                         out + params_sz, out + params_sz + (size_t)Bn * Zn);
    latent2<<<dim3(8, 24), 256>>>(init_W, init_b, dec_Wx, dec_b);
    dec_persist<<<128, 256, DEC_SMEM>>>(data, dec_Wx, dec_Wh);
    mix_kernel<<<TB / 32, 256>>>(mix_W, mix_b, out);
}

// round 15
// speedup vs baseline: 1.2152x; 1.2152x over previous
#include <cuda_runtime.h>
#include <cuda_bf16.h>
#include <math.h>

#define Bn 256
#define Tn 250
#define Zn 128
#define Hn 256
#define Dn 512
#define Kn 20
#define Pn 123
#define TB (Tn*Bn)

typedef unsigned long long ull;
typedef unsigned int u32;
typedef unsigned short u16;

__device__ u32  g_hfH[2][Bn*Hn/2];
__device__ u32  g_hfL[2][Bn*Hn/2];
__device__ u32  g_hbH[2][Bn*Hn/2];
__device__ u32  g_hbL[2][Bn*Hn/2];
__device__ u32  g_hdH[2][Bn*Dn/2];
__device__ u32  g_hdL[2][Bn*Dn/2];
__device__ u32  g_hsH[(size_t)TB*(Dn/2)];
__device__ u32  g_hsL[(size_t)TB*(Dn/2)];
__device__ float g_z  [Bn*Zn];
__device__ float g_zgT[4*Dn*Bn];
__device__ float g_cdT[Dn*Bn];
__device__ int   g_pflag[256];
__device__ int   g_done[16];

// ---- fast transcendentals ----
__device__ __forceinline__ float ex2a(float x){ float y; asm("ex2.approx.f32 %0,%1;":"=f"(y):"f"(x)); return y; }
__device__ __forceinline__ float rcpa(float x){ float y; asm("rcp.approx.f32 %0,%1;":"=f"(y):"f"(x)); return y; }
__device__ __forceinline__ float sigf(float x){ return rcpa(1.0f + ex2a(-1.4426950408889634f * x)); }
__device__ __forceinline__ float tanha(float x){ return 1.0f - 2.0f * rcpa(ex2a(2.8853900817779268f * x) + 1.0f); }

__device__ __forceinline__ void ffma2(ull& d, ull a, ull b) {
    asm("fma.rn.f32x2 %0, %1, %2, %0;" : "+l"(d) : "l"(a), "l"(b));
}
__device__ __forceinline__ ull dup2(float w) {
    ull r; u32 u = __float_as_uint(w);
    asm("mov.b64 %0, {%1, %1};" : "=l"(r) : "r"(u));
    return r;
}
__device__ __forceinline__ float2 unpk(ull v) {
    float2 f; asm("mov.b64 {%0, %1}, %2;" : "=f"(f.x), "=f"(f.y) : "l"(v));
    return f;
}
__device__ __forceinline__ int ld_acq(const int* p) {
    int v; asm volatile("ld.acquire.gpu.global.s32 %0, [%1];" : "=r"(v) : "l"(p) : "memory");
    return v;
}
__device__ __forceinline__ void red_rel(int* p) {
    asm volatile("red.release.gpu.global.add.s32 [%0], 1;" :: "l"(p) : "memory");
}
__device__ __forceinline__ void wait_all(const int* flags, int n, int t) {
    int lane = threadIdx.x & 31;
    if (lane < n) { while (ld_acq(flags + lane) < t) { } }
    __syncwarp();
}
__device__ __forceinline__ u32 pack_hi(float a, float b, u32& lo) {
    __nv_bfloat16 ha = __float2bfloat16_rn(a), hb = __float2bfloat16_rn(b);
    __nv_bfloat16 la = __float2bfloat16_rn(a - __bfloat162float(ha));
    __nv_bfloat16 lb = __float2bfloat16_rn(b - __bfloat162float(hb));
    __nv_bfloat162 ph(ha, hb), pl(la, lb);
    lo = *(u32*)&pl;
    return *(u32*)&ph;
}
__device__ __forceinline__ void mma16(float* c, u32 a0, u32 a1, u32 a2, u32 a3,
                                      u32 b0, u32 b1) {
    asm("mma.sync.aligned.m16n8k16.row.col.f32.bf16.bf16.f32 "
        "{%0,%1,%2,%3}, {%4,%5,%6,%7}, {%8,%9}, {%0,%1,%2,%3};"
        : "+f"(c[0]), "+f"(c[1]), "+f"(c[2]), "+f"(c[3])
        : "r"(a0), "r"(a1), "r"(a2), "r"(a3), "r"(b0), "r"(b1));
}

#define WP 72
#define AP 36

// Pair-local staging + named pair barriers. TERM-MAJOR inner loop: B frags
// for all 4 nb cells are hoisted, then hh/hl/lh passes each sweep nb=0..3,
// so dependent MMAs on one accumulator are 4 apart instead of back-to-back.
template<int CN>
__device__ __forceinline__ void mma_steps(
    float (&acc)[4][4], const u32* rh, const u32* rl,
    u32* Ab, const u32* Whi, const u32* Wlo,
    int srow, int sw, int ra0, int ra1, int n0, int g, int t4)
{
    const int bid = 1 + ((threadIdx.x >> 5) & 3);
    uint4 ph0, ph1, pl0, pl1;
    ph0 = __ldcg((const uint4*)&rh[sw * 4]);  ph1 = __ldcg((const uint4*)&rh[sw * 4 + 16]);
    pl0 = __ldcg((const uint4*)&rl[sw * 4]);  pl1 = __ldcg((const uint4*)&rl[sw * 4 + 16]);
    #pragma unroll 1
    for (int c = 0; c < CN; c++) {
        u32* Ah = Ab + (c & 1) * 2304;
        u32* Al = Ab + 4608 + (c & 1) * 2304;
        *(uint4*)&Ah[srow * AP + sw * 4]      = ph0;
        *(uint4*)&Ah[srow * AP + sw * 4 + 16] = ph1;
        *(uint4*)&Al[srow * AP + sw * 4]      = pl0;
        *(uint4*)&Al[srow * AP + sw * 4 + 16] = pl1;
        if (c < CN - 1) {
            ph0 = __ldcg((const uint4*)&rh[(c + 1) * 32 + sw * 4]);
            ph1 = __ldcg((const uint4*)&rh[(c + 1) * 32 + sw * 4 + 16]);
            pl0 = __ldcg((const uint4*)&rl[(c + 1) * 32 + sw * 4]);
            pl1 = __ldcg((const uint4*)&rl[(c + 1) * 32 + sw * 4 + 16]);
        }
        asm volatile("bar.sync %0, 64;" :: "r"(bid) : "memory");
        #pragma unroll
        for (int s = 0; s < 4; s++) {
            int o = 8 * s;
            u32 ah0 = Ah[ra0 + o], ah1 = Ah[ra1 + o], ah2 = Ah[ra0 + o + 4], ah3 = Ah[ra1 + o + 4];
            u32 al0 = Al[ra0 + o], al1 = Al[ra1 + o], al2 = Al[ra0 + o + 4], al3 = Al[ra1 + o + 4];
            const u32* bh = Whi + (c * 32 + o + t4) * WP + n0 + g;
            const u32* bl = Wlo + (c * 32 + o + t4) * WP + n0 + g;
            u32 b0h[4], b1h[4], b0l[4], b1l[4];
            #pragma unroll
            for (int nb = 0; nb < 4; nb++) {
                b0h[nb] = bh[8 * nb]; b1h[nb] = bh[8 * nb + 4 * WP];
                b0l[nb] = bl[8 * nb]; b1l[nb] = bl[8 * nb + 4 * WP];
            }
            #pragma unroll
            for (int nb = 0; nb < 4; nb++)
                mma16(acc[nb], ah0, ah1, ah2, ah3, b0h[nb], b1h[nb]);
            #pragma unroll
            for (int nb = 0; nb < 4; nb++)
                mma16(acc[nb], ah0, ah1, ah2, ah3, b0l[nb], b1l[nb]);
            #pragma unroll
            for (int nb = 0; nb < 4; nb++)
                mma16(acc[nb], al0, al1, al2, al3, b0h[nb], b1h[nb]);
        }
    }
}

// gather the 4 gates of a unit into one lane (cols packed unit*4+gate)
__device__ __forceinline__ float4 gather_gates(const float* a4, int rowSel) {
    float sx = rowSel ? a4[0] : a4[2];
    float sy = rowSel ? a4[1] : a4[3];
    float rx = __shfl_xor_sync(0xffffffffu, sx, 1);
    float ry = __shfl_xor_sync(0xffffffffu, sy, 1);
    return rowSel ? make_float4(rx, ry, a4[2], a4[3])
                  : make_float4(a4[0], a4[1], rx, ry);
}

// =================== persistent encoder =====================================
#define ENC_SMEM 122880
__global__ __launch_bounds__(256) void enc_persist(
    const float* __restrict__ data,
    const float* __restrict__ Wx_f, const float* __restrict__ Wh_f, const float* __restrict__ b_f,
    const float* __restrict__ Wx_b, const float* __restrict__ Wh_b, const float* __restrict__ b_b)
{
    extern __shared__ u32 sm[];
    u32*  Whi = sm;
    u32*  Wlo = sm + 9216;
    u32*  Ab  = sm + 18432;
    float* Wxs = (float*)(sm + 27648);
    float* Xsm = (float*)(sm + 27968);

    const int tid = threadIdx.x, lane = tid & 31, warp = tid >> 5;
    const int g = lane >> 2, t4 = lane & 3;
    const int m0 = (warp & 3) * 16, n0 = (warp >> 2) * 32;
    const int dir = blockIdx.x >> 6, bt = (blockIdx.x >> 4) & 3, ut = blockIdx.x & 15;
    const int b0 = bt * 64, u0 = ut * 16;

    const float* __restrict__ Wh = dir ? Wh_b : Wh_f;
    const float* __restrict__ Wx = dir ? Wx_b : Wx_f;
    const float* __restrict__ bb = dir ? b_b  : b_f;
    u32* hH[2] = { dir ? g_hbH[0] : g_hfH[0], dir ? g_hbH[1] : g_hfH[1] };
    u32* hL[2] = { dir ? g_hbL[0] : g_hfL[0], dir ? g_hbL[1] : g_hfL[1] };
    int* fbase  = g_pflag + (dir * 4 + bt) * 16;
    int* done   = &g_done[dir * 4 + bt];

    for (int i = tid; i < 8192; i += 256) {
        int kp = i >> 6, c = i & 63, ul = c >> 2, gate = c & 3;
        float w0 = __ldg(&Wh[(2 * kp)     * 1024 + gate * Hn + u0 + ul]);
        float w1 = __ldg(&Wh[(2 * kp + 1) * 1024 + gate * Hn + u0 + ul]);
        u32 lo, hi = pack_hi(w0, w1, lo);
        Whi[kp * WP + c] = hi; Wlo[kp * WP + c] = lo;
    }
    for (int i = tid; i < 320; i += 256) {
        int j = i >> 6, c = i & 63, ul = c >> 2, gate = c & 3;
        Wxs[i] = __ldg(&Wx[j * 1024 + gate * Hn + u0 + ul]);
    }

    const int rowSel = t4 & 1;
    const int upart  = t4 >> 1;
    const int myrow  = m0 + g + 8 * rowSel;
    const int nhalf  = n0 >> 5;
    const int srow = ((warp & 3) << 4) + ((warp >> 2) << 3) + (lane >> 2);
    const int sw = lane & 3;
    const int ra0 = (m0 + g) * AP + t4, ra1 = (m0 + g + 8) * AP + t4;

    float4 bsv[4];
    #pragma unroll
    for (int nb = 0; nb < 4; nb++) {
        int u = u0 + 8 * nhalf + 2 * nb + upart;
        bsv[nb] = make_float4(__ldg(&bb[u]), __ldg(&bb[Hn + u]),
                              __ldg(&bb[2 * Hn + u]), __ldg(&bb[3 * Hn + u]));
    }
    float creg[4] = {0, 0, 0, 0};

    if (tid < 64) {
        int xtime = dir ? Tn : 1;
        #pragma unroll
        for (int j = 0; j < 5; j++)
            Xsm[tid * 5 + j] = __ldg(&data[(size_t)(b0 + tid) * 1255 + xtime * 5 + j]);
    }
    __syncthreads();

    for (int t = 0; t < Tn; t++) {
        const u32* hiIn = hH[t & 1]; const u32* loIn = hL[t & 1];
        u32* hiOut = hH[(t + 1) & 1]; u32* loOut = hL[(t + 1) & 1];

        float acc[4][4] = {};
        if (t > 0) {
            wait_all(fbase, 16, t);
            mma_steps<4>(acc, &hiIn[(size_t)(b0 + srow) * 128], &loIn[(size_t)(b0 + srow) * 128],
                         Ab, Whi, Wlo, srow, sw, ra0, ra1, n0, g, t4);
        }

        const float* xr = &Xsm[(t & 1) * 320 + myrow * 5];
        float x0 = xr[0], x1 = xr[1], x2 = xr[2], x3 = xr[3], x4 = xr[4];
        u32 hiw[4], low[4];
        #pragma unroll
        for (int nb = 0; nb < 4; nb++) {
            float4 p = gather_gates(acc[nb], rowSel);
            int uc = 8 * nhalf + 2 * nb + upart;
            p.x += bsv[nb].x; p.y += bsv[nb].y; p.z += bsv[nb].z; p.w += bsv[nb].w;
            const float* wx = &Wxs[4 * uc];
            p.x = fmaf(x0, wx[0], p.x); p.y = fmaf(x0, wx[1], p.y);
            p.z = fmaf(x0, wx[2], p.z); p.w = fmaf(x0, wx[3], p.w);
            p.x = fmaf(x1, wx[64], p.x); p.y = fmaf(x1, wx[65], p.y);
            p.z = fmaf(x1, wx[66], p.z); p.w = fmaf(x1, wx[67], p.w);
            p.x = fmaf(x2, wx[128], p.x); p.y = fmaf(x2, wx[129], p.y);
            p.z = fmaf(x2, wx[130], p.z); p.w = fmaf(x2, wx[131], p.w);
            p.x = fmaf(x3, wx[192], p.x); p.y = fmaf(x3, wx[193], p.y);
            p.z = fmaf(x3, wx[194], p.z); p.w = fmaf(x3, wx[195], p.w);
            p.x = fmaf(x4, wx[256], p.x); p.y = fmaf(x4, wx[257], p.y);
            p.z = fmaf(x4, wx[258], p.z); p.w = fmaf(x4, wx[259], p.w);
            float cn = sigf(p.y) * creg[nb] + sigf(p.x) * tanha(p.z);
            float h = sigf(p.w) * tanha(cn);
            creg[nb] = cn;
            __nv_bfloat16 hb = __float2bfloat16_rn(h);
            __nv_bfloat16 lb = __float2bfloat16_rn(h - __bfloat162float(hb));
            u32 hl = (u32)*(u16*)&hb | ((u32)*(u16*)&lb << 16);
            u32 pr = __shfl_xor_sync(0xffffffffu, hl, 2);
            hiw[nb] = (hl & 0xFFFFu) | ((pr & 0xFFFFu) << 16);
            low[nb] = (hl >> 16) | (pr & 0xFFFF0000u);
        }
        if (upart == 0) {
            size_t base = (size_t)(b0 + myrow) * 128 + ut * 8 + 4 * nhalf;
            __stcg((uint4*)&hiOut[base], make_uint4(hiw[0], hiw[1], hiw[2], hiw[3]));
            __stcg((uint4*)&loOut[base], make_uint4(low[0], low[1], low[2], low[3]));
        }
        if (tid < 64 && t + 1 < Tn) {
            int xtime = dir ? (Tn - t - 1) : (t + 2);
            #pragma unroll
            for (int j = 0; j < 5; j++)
                Xsm[((t + 1) & 1) * 320 + tid * 5 + j] =
                    __ldg(&data[(size_t)(b0 + tid) * 1255 + xtime * 5 + j]);
        }
        __syncthreads();
        if (tid == 0 && t < Tn - 1) red_rel(fbase + ut);
    }
    if (tid == 0) {
        int old = atomicAdd(done, 1);
        if (old == 15) {
            for (int j = 0; j < 16; j++) atomicExch(fbase + j, 0);
            atomicExch(done, 0);
        }
    }
}

// =================== persistent decoder =====================================
#define DEC_SMEM 188160
__global__ __launch_bounds__(256) void dec_persist(
    const float* __restrict__ data,
    const float* __restrict__ dec_Wx, const float* __restrict__ Wh)
{
    extern __shared__ u32 sm[];
    u32*  Whi = sm;
    u32*  Wlo = sm + 18432;
    u32*  Ab  = sm + 36864;
    float* Wxs = (float*)(sm + 46080);
    float* Xsm = (float*)(sm + 46400);

    const int tid = threadIdx.x, lane = tid & 31, warp = tid >> 5;
    const int g = lane >> 2, t4 = lane & 3;
    const int m0 = (warp & 3) * 16, n0 = (warp >> 2) * 32;
    const int bt = blockIdx.x >> 5, ut = blockIdx.x & 31;
    const int b0 = bt * 64, u0 = ut * 16;
    int* fbase = g_pflag + 128 + bt * 32;
    int* done  = &g_done[8 + bt];

    for (int i = tid; i < 16384; i += 256) {
        int kp = i >> 6, c = i & 63, ul = c >> 2, gate = c & 3;
        float w0 = __ldg(&Wh[(2 * kp)     * 2048 + gate * Dn + u0 + ul]);
        float w1 = __ldg(&Wh[(2 * kp + 1) * 2048 + gate * Dn + u0 + ul]);
        u32 lo, hi = pack_hi(w0, w1, lo);
        Whi[kp * WP + c] = hi; Wlo[kp * WP + c] = lo;
    }
    for (int i = tid; i < 320; i += 256) {
        int j = i >> 6, c = i & 63, ul = c >> 2, gate = c & 3;
        Wxs[i] = __ldg(&dec_Wx[j * 2048 + gate * Dn + u0 + ul]);
    }

    const int rowSel = t4 & 1;
    const int upart  = t4 >> 1;
    const int myrow  = m0 + g + 8 * rowSel;
    const int nhalf  = n0 >> 5;
    const int srow = ((warp & 3) << 4) + ((warp >> 2) << 3) + (lane >> 2);
    const int sw = lane & 3;
    const int ra0 = (m0 + g) * AP + t4, ra1 = (m0 + g + 8) * AP + t4;

    float4 zgv[4]; float creg[4];
    #pragma unroll
    for (int nb = 0; nb < 4; nb++) {
        int u = u0 + 8 * nhalf + 2 * nb + upart;
        int b = b0 + myrow;
        zgv[nb] = make_float4(g_zgT[((size_t)0 * Dn + u) * Bn + b],
                              g_zgT[((size_t)1 * Dn + u) * Bn + b],
                              g_zgT[((size_t)2 * Dn + u) * Bn + b],
                              g_zgT[((size_t)3 * Dn + u) * Bn + b]);
        creg[nb] = g_cdT[(size_t)u * Bn + b];
    }

    if (tid < 64) {
        #pragma unroll
        for (int j = 0; j < 5; j++)
            Xsm[tid * 5 + j] = __ldg(&data[(size_t)(b0 + tid) * 1255 + 0 * 5 + j]);
    }
    __syncthreads();

    for (int t = 0; t < Tn; t++) {
        const u32* hiIn = g_hdH[t & 1]; const u32* loIn = g_hdL[t & 1];
        u32* hiOut = g_hdH[(t + 1) & 1]; u32* loOut = g_hdL[(t + 1) & 1];

        float acc[4][4] = {};
        wait_all(fbase, 32, t);
        mma_steps<8>(acc, &hiIn[(size_t)(b0 + srow) * 256], &loIn[(size_t)(b0 + srow) * 256],
                     Ab, Whi, Wlo, srow, sw, ra0, ra1, n0, g, t4);

        const float* xr = &Xsm[(t & 1) * 320 + myrow * 5];
        float x0 = xr[0], x1 = xr[1], x2 = xr[2], x3 = xr[3], x4 = xr[4];
        u32 hiw[4], low[4];
        #pragma unroll
        for (int nb = 0; nb < 4; nb++) {
            float4 p = gather_gates(acc[nb], rowSel);
            int uc = 8 * nhalf + 2 * nb + upart;
            p.x += zgv[nb].x; p.y += zgv[nb].y; p.z += zgv[nb].z; p.w += zgv[nb].w;
            const float* wx = &Wxs[4 * uc];
            p.x = fmaf(x0, wx[0], p.x); p.y = fmaf(x0, wx[1], p.y);
            p.z = fmaf(x0, wx[2], p.z); p.w = fmaf(x0, wx[3], p.w);
            p.x = fmaf(x1, wx[64], p.x); p.y = fmaf(x1, wx[65], p.y);
            p.z = fmaf(x1, wx[66], p.z); p.w = fmaf(x1, wx[67], p.w);
            p.x = fmaf(x2, wx[128], p.x); p.y = fmaf(x2, wx[129], p.y);
            p.z = fmaf(x2, wx[130], p.z); p.w = fmaf(x2, wx[131], p.w);
            p.x = fmaf(x3, wx[192], p.x); p.y = fmaf(x3, wx[193], p.y);
            p.z = fmaf(x3, wx[194], p.z); p.w = fmaf(x3, wx[195], p.w);
            p.x = fmaf(x4, wx[256], p.x); p.y = fmaf(x4, wx[257], p.y);
            p.z = fmaf(x4, wx[258], p.z); p.w = fmaf(x4, wx[259], p.w);
            float cn = sigf(p.y) * creg[nb] + sigf(p.x) * tanha(p.z);
            float h = sigf(p.w) * tanha(cn);
            creg[nb] = cn;
            __nv_bfloat16 hb = __float2bfloat16_rn(h);
            __nv_bfloat16 lb = __float2bfloat16_rn(h - __bfloat162float(hb));
            u32 hl = (u32)*(u16*)&hb | ((u32)*(u16*)&lb << 16);
            u32 pr = __shfl_xor_sync(0xffffffffu, hl, 2);
            hiw[nb] = (hl & 0xFFFFu) | ((pr & 0xFFFFu) << 16);
            low[nb] = (hl >> 16) | (pr & 0xFFFF0000u);
        }
        if (upart == 0) {
            size_t base = (size_t)(b0 + myrow) * 256 + ut * 8 + 4 * nhalf;
            uint4 hv = make_uint4(hiw[0], hiw[1], hiw[2], hiw[3]);
            uint4 lv = make_uint4(low[0], low[1], low[2], low[3]);
            __stcg((uint4*)&hiOut[base], hv);
            __stcg((uint4*)&loOut[base], lv);
            size_t hb2 = ((size_t)t * Bn + b0 + myrow) * 256 + ut * 8 + 4 * nhalf;
            __stcg((uint4*)&g_hsH[hb2], hv);
            __stcg((uint4*)&g_hsL[hb2], lv);
        }
        if (tid < 64 && t + 1 < Tn) {
            #pragma unroll
            for (int j = 0; j < 5; j++)
                Xsm[((t + 1) & 1) * 320 + tid * 5 + j] =
                    __ldg(&data[(size_t)(b0 + tid) * 1255 + (t + 1) * 5 + j]);
        }
        __syncthreads();
        if (tid == 0 && t < Tn - 1) red_rel(fbase + ut);
    }
    if (tid == 0) {
        int old = atomicAdd(done, 1);
        if (old == 31) {
            for (int j = 0; j < 32; j++) atomicExch(fbase + j, 0);
            atomicExch(done, 0);
        }
    }
}

// =================== latent stages ==========================================
__global__ void latent1(const float* __restrict__ W, const float* __restrict__ bias,
                        const float* __restrict__ eps,
                        float* __restrict__ zm, float* __restrict__ zl)
{
    int b = blockIdx.x, j = threadIdx.x;
    const __nv_bfloat16* fh = (const __nv_bfloat16*)g_hfH[0];
    const __nv_bfloat16* fl = (const __nv_bfloat16*)g_hfL[0];
    const __nv_bfloat16* bh = (const __nv_bfloat16*)g_hbH[0];
    const __nv_bfloat16* bl = (const __nv_bfloat16*)g_hbL[0];
    float sm = bias[j], sl = bias[j + Zn];
    for (int k = 0; k < Hn; k++) {
        float a = __bfloat162float(fh[b * Hn + k]) + __bfloat162float(fl[b * Hn + k]);
        sm = fmaf(a, W[k * (2 * Zn) + j], sm);
        sl = fmaf(a, W[k * (2 * Zn) + Zn + j], sl);
    }
    for (int k = 0; k < Hn; k++) {
        float a = __bfloat162float(bh[b * Hn + k]) + __bfloat162float(bl[b * Hn + k]);
        sm = fmaf(a, W[(Hn + k) * (2 * Zn) + j], sm);
        sl = fmaf(a, W[(Hn + k) * (2 * Zn) + Zn + j], sl);
    }
    zm[b * Zn + j] = sm;
    zl[b * Zn + j] = sl;
    g_z[b * Zn + j] = sm + expf(0.5f * sl) * eps[b * Zn + j];
}

__global__ __launch_bounds__(256) void latent2(
    const float* __restrict__ init_W, const float* __restrict__ init_b,
    const float* __restrict__ dec_Wx, const float* __restrict__ dec_b)
{
    __shared__ float zs[32][Zn];
    const int tid = threadIdx.x;
    const int tx = tid & 31, ty = tid >> 5;
    const int b0 = blockIdx.x * 32;
    const int col0 = blockIdx.y * 128;
    const bool isInit = (col0 < 2 * Dn);

    for (int i = tid; i < 32 * Zn; i += 256)
        zs[i >> 7][i & 127] = g_z[(b0 + (i >> 7)) * Zn + (i & 127)];
    __syncthreads();

    const int col = col0 + tx * 4;
    const float* Wcol = isInit ? (init_W + col) : (dec_Wx + 5 * (4 * Dn) + (col - 2 * Dn));
    const int wstride = isInit ? (2 * Dn) : (4 * Dn);

    float acc[4][4] = {};
    #pragma unroll 4
    for (int k = 0; k < Zn; k++) {
        float4 w = *(const float4*)&Wcol[k * wstride];
        float a0 = zs[ty * 4 + 0][k], a1 = zs[ty * 4 + 1][k];
        float a2 = zs[ty * 4 + 2][k], a3 = zs[ty * 4 + 3][k];
        acc[0][0] = fmaf(a0, w.x, acc[0][0]); acc[0][1] = fmaf(a0, w.y, acc[0][1]);
        acc[0][2] = fmaf(a0, w.z, acc[0][2]); acc[0][3] = fmaf(a0, w.w, acc[0][3]);
        acc[1][0] = fmaf(a1, w.x, acc[1][0]); acc[1][1] = fmaf(a1, w.y, acc[1][1]);
        acc[1][2] = fmaf(a1, w.z, acc[1][2]); acc[1][3] = fmaf(a1, w.w, acc[1][3]);
        acc[2][0] = fmaf(a2, w.x, acc[2][0]); acc[2][1] = fmaf(a2, w.y, acc[2][1]);
        acc[2][2] = fmaf(a2, w.z, acc[2][2]); acc[2][3] = fmaf(a2, w.w, acc[2][3]);
        acc[3][0] = fmaf(a3, w.x, acc[3][0]); acc[3][1] = fmaf(a3, w.y, acc[3][1]);
        acc[3][2] = fmaf(a3, w.z, acc[3][2]); acc[3][3] = fmaf(a3, w.w, acc[3][3]);
    }

    __nv_bfloat16* hH = (__nv_bfloat16*)g_hdH[0];
    __nv_bfloat16* hL = (__nv_bfloat16*)g_hdL[0];
    #pragma unroll
    for (int r = 0; r < 4; r++) {
        int b = b0 + ty * 4 + r;
        #pragma unroll
        for (int c = 0; c < 4; c++) {
            int cc = col + c;
            if (isInit) {
                float v = tanhf(acc[r][c] + init_b[cc]);
                if (cc < Dn) {
                    __nv_bfloat16 hb = __float2bfloat16_rn(v);
                    hH[(size_t)b * Dn + cc] = hb;
                    hL[(size_t)b * Dn + cc] = __float2bfloat16_rn(v - __bfloat162float(hb));
                } else {
                    g_cdT[(size_t)(cc - Dn) * Bn + b] = v;
                }
            } else {
                int c2 = cc - 2 * Dn;
                g_zgT[(size_t)c2 * Bn + b] = acc[r][c] + dec_b[c2];
            }
        }
    }
}

// =================== output head ============================================
__global__ __launch_bounds__(256) void mix_kernel(
    const float* __restrict__ Wm, const float* __restrict__ bm, float* __restrict__ out)
{
    __shared__ __align__(16) float As[32][34];
    __shared__ __align__(16) float Ws[32][128];
    __shared__ float ys[32 * 129];
    const int tid = threadIdx.x;
    const int tx = tid & 31, ty = tid >> 5;
    const int row0 = blockIdx.x * 32;
    ull acc[2][4] = {};

    for (int k0 = 0; k0 < Dn; k0 += 32) {
        __syncthreads();
        #pragma unroll
        for (int it = 0; it < 2; it++) {
            int idx = tid + it * 256;
            int r = idx >> 4, j = idx & 15;
            u32 hi = g_hsH[(size_t)(row0 + r) * 256 + (k0 >> 1) + j];
            u32 lo = g_hsL[(size_t)(row0 + r) * 256 + (k0 >> 1) + j];
            __nv_bfloat162 h2 = *(__nv_bfloat162*)&hi;
            __nv_bfloat162 l2 = *(__nv_bfloat162*)&lo;
            As[2 * j][r]     = __bfloat162float(h2.x) + __bfloat162float(l2.x);
            As[2 * j + 1][r] = __bfloat162float(h2.y) + __bfloat162float(l2.y);
        }
        for (int i = tid; i < 32 * 128; i += 256) {
            int k = i >> 7, c = i & 127;
            Ws[k][c] = (c < Pn) ? Wm[(k0 + k) * Pn + c] : 0.f;
        }
        __syncthreads();
        #pragma unroll 4
        for (int k = 0; k < 32; k++) {
            ull a01 = *(const ull*)&As[k][ty * 4];
            ull a23 = *(const ull*)&As[k][ty * 4 + 2];
            float4 w = *(const float4*)&Ws[k][tx * 4];
            ull w0 = dup2(w.x), w1 = dup2(w.y), w2 = dup2(w.z), w3 = dup2(w.w);
            ffma2(acc[0][0], a01, w0); ffma2(acc[0][1], a01, w1);
            ffma2(acc[0][2], a01, w2); ffma2(acc[0][3], a01, w3);
            ffma2(acc[1][0], a23, w0); ffma2(acc[1][1], a23, w1);
            ffma2(acc[1][2], a23, w2); ffma2(acc[1][3], a23, w3);
        }
    }

    #pragma unroll
    for (int pr = 0; pr < 2; pr++)
        #pragma unroll
        for (int c = 0; c < 4; c++) {
            float2 v = unpk(acc[pr][c]);
            int cc = tx * 4 + c;
            float bias = (cc < Pn) ? bm[cc] : 0.f;
            ys[(ty * 4 + pr * 2 + 0) * 129 + cc] = v.x + bias;
            ys[(ty * 4 + pr * 2 + 1) * 129 + cc] = v.y + bias;
        }
    __syncthreads();

    if (tid < 32) {
        int row = row0 + tid;
        int tt = row >> 8, bb2 = row & 255;
        float* o = out + ((size_t)bb2 * Tn + tt) * Pn;
        const float* y = &ys[tid * 129];
        float m = y[0];
        #pragma unroll
        for (int j = 1; j < Kn; j++) m = fmaxf(m, y[j]);
        float e[Kn]; float sum = 0.f;
        #pragma unroll
        for (int j = 0; j < Kn; j++) { e[j] = expf(y[j] - m); sum += e[j]; }
        float inv = 1.f / sum;
        #pragma unroll
        for (int j = 0; j < Kn; j++) o[j] = e[j] * inv;
        #pragma unroll
        for (int j = Kn; j < 3 * Kn; j++) o[j] = y[j];
        #pragma unroll
        for (int j = 3 * Kn; j < 5 * Kn; j++) o[j] = expf(y[j]);
        #pragma unroll
        for (int j = 5 * Kn; j < 6 * Kn; j++) o[j] = tanhf(y[j]);
        o[120] = y[120]; o[121] = y[121]; o[122] = y[122];
    }
}

// =================== launcher ================================================
extern "C" void kernel_launch(void* const* d_in, const int* in_sizes, int n_in,
                              void* d_out, int out_size)
{
    (void)in_sizes; (void)n_in; (void)out_size;
    const float* data      = (const float*)d_in[0];
    const float* eps       = (const float*)d_in[1];
    const float* enc_Wx_f  = (const float*)d_in[2];
    const float* enc_Wh_f  = (const float*)d_in[3];
    const float* enc_b_f   = (const float*)d_in[4];
    const float* enc_Wx_b  = (const float*)d_in[5];
    const float* enc_Wh_b  = (const float*)d_in[6];
    const float* enc_b_b   = (const float*)d_in[7];
    const float* enc_out_W = (const float*)d_in[8];
    const float* enc_out_b = (const float*)d_in[9];
    const float* init_W    = (const float*)d_in[10];
    const float* init_b    = (const float*)d_in[11];
    const float* dec_Wx    = (const float*)d_in[12];
    const float* dec_Wh    = (const float*)d_in[13];
    const float* dec_b     = (const float*)d_in[14];
    const float* mix_W     = (const float*)d_in[15];
    const float* mix_b     = (const float*)d_in[16];
    float* out = (float*)d_out;

    cudaFuncSetAttribute(enc_persist, cudaFuncAttributeMaxDynamicSharedMemorySize, ENC_SMEM);
    cudaFuncSetAttribute(dec_persist, cudaFuncAttributeMaxDynamicSharedMemorySize, DEC_SMEM);

    const size_t params_sz = (size_t)Bn * Tn * Pn;

    enc_persist<<<128, 256, ENC_SMEM>>>(data, enc_Wx_f, enc_Wh_f, enc_b_f,
                                        enc_Wx_b, enc_Wh_b, enc_b_b);
    latent1<<<Bn, 128>>>(enc_out_W, enc_out_b, eps,
                         out + params_sz, out + params_sz + (size_t)Bn * Zn);
    latent2<<<dim3(8, 24), 256>>>(init_W, init_b, dec_Wx, dec_b);
    dec_persist<<<128, 256, DEC_SMEM>>>(data, dec_Wx, dec_Wh);
    mix_kernel<<<TB / 32, 256>>>(mix_W, mix_b, out);
}

// round 16
// speedup vs baseline: 1.2622x; 1.0386x over previous
#include <cuda_runtime.h>
#include <cuda_bf16.h>
#include <math.h>

#define Bn 256
#define Tn 250
#define Zn 128
#define Hn 256
#define Dn 512
#define Kn 20
#define Pn 123
#define TB (Tn*Bn)

typedef unsigned long long ull;
typedef unsigned int u32;
typedef unsigned short u16;

__device__ u32  g_hfH[2][Bn*Hn/2];
__device__ u32  g_hfL[2][Bn*Hn/2];
__device__ u32  g_hbH[2][Bn*Hn/2];
__device__ u32  g_hbL[2][Bn*Hn/2];
__device__ u32  g_hdH[2][Bn*Dn/2];
__device__ u32  g_hdL[2][Bn*Dn/2];
__device__ u32  g_hsH[(size_t)TB*(Dn/2)];
__device__ u32  g_hsL[(size_t)TB*(Dn/2)];
__device__ u32  g_WmH[256*128];     // prepacked mix_W bf16 hi, [kp][col]
__device__ u32  g_WmL[256*128];
__device__ float g_z  [Bn*Zn];
__device__ float g_zgT[4*Dn*Bn];
__device__ float g_cdT[Dn*Bn];
__device__ int   g_pflag[256];
__device__ int   g_done[16];

// ---- fast transcendentals ----
__device__ __forceinline__ float ex2a(float x){ float y; asm("ex2.approx.f32 %0,%1;":"=f"(y):"f"(x)); return y; }
__device__ __forceinline__ float rcpa(float x){ float y; asm("rcp.approx.f32 %0,%1;":"=f"(y):"f"(x)); return y; }
__device__ __forceinline__ float sigf(float x){ return rcpa(1.0f + ex2a(-1.4426950408889634f * x)); }
__device__ __forceinline__ float tanha(float x){ return 1.0f - 2.0f * rcpa(ex2a(2.8853900817779268f * x) + 1.0f); }

__device__ __forceinline__ int ld_acq(const int* p) {
    int v; asm volatile("ld.acquire.gpu.global.s32 %0, [%1];" : "=r"(v) : "l"(p) : "memory");
    return v;
}
__device__ __forceinline__ void red_rel(int* p) {
    asm volatile("red.release.gpu.global.add.s32 [%0], 1;" :: "l"(p) : "memory");
}
__device__ __forceinline__ void wait_all(const int* flags, int n, int t) {
    int lane = threadIdx.x & 31;
    if (lane < n) { while (ld_acq(flags + lane) < t) { } }
    __syncwarp();
}
__device__ __forceinline__ u32 pack_hi(float a, float b, u32& lo) {
    __nv_bfloat16 ha = __float2bfloat16_rn(a), hb = __float2bfloat16_rn(b);
    __nv_bfloat16 la = __float2bfloat16_rn(a - __bfloat162float(ha));
    __nv_bfloat16 lb = __float2bfloat16_rn(b - __bfloat162float(hb));
    __nv_bfloat162 ph(ha, hb), pl(la, lb);
    lo = *(u32*)&pl;
    return *(u32*)&ph;
}
__device__ __forceinline__ void mma16(float* c, u32 a0, u32 a1, u32 a2, u32 a3,
                                      u32 b0, u32 b1) {
    asm("mma.sync.aligned.m16n8k16.row.col.f32.bf16.bf16.f32 "
        "{%0,%1,%2,%3}, {%4,%5,%6,%7}, {%8,%9}, {%0,%1,%2,%3};"
        : "+f"(c[0]), "+f"(c[1]), "+f"(c[2]), "+f"(c[3])
        : "r"(a0), "r"(a1), "r"(a2), "r"(a3), "r"(b0), "r"(b1));
}

#define WP 72
#define AP 36

// Pair-local staging + named pair barriers. TERM-MAJOR inner loop.
template<int CN>
__device__ __forceinline__ void mma_steps(
    float (&acc)[4][4], const u32* rh, const u32* rl,
    u32* Ab, const u32* Whi, const u32* Wlo,
    int srow, int sw, int ra0, int ra1, int n0, int g, int t4)
{
    const int bid = 1 + ((threadIdx.x >> 5) & 3);
    uint4 ph0, ph1, pl0, pl1;
    ph0 = __ldcg((const uint4*)&rh[sw * 4]);  ph1 = __ldcg((const uint4*)&rh[sw * 4 + 16]);
    pl0 = __ldcg((const uint4*)&rl[sw * 4]);  pl1 = __ldcg((const uint4*)&rl[sw * 4 + 16]);
    #pragma unroll 1
    for (int c = 0; c < CN; c++) {
        u32* Ah = Ab + (c & 1) * 2304;
        u32* Al = Ab + 4608 + (c & 1) * 2304;
        *(uint4*)&Ah[srow * AP + sw * 4]      = ph0;
        *(uint4*)&Ah[srow * AP + sw * 4 + 16] = ph1;
        *(uint4*)&Al[srow * AP + sw * 4]      = pl0;
        *(uint4*)&Al[srow * AP + sw * 4 + 16] = pl1;
        if (c < CN - 1) {
            ph0 = __ldcg((const uint4*)&rh[(c + 1) * 32 + sw * 4]);
            ph1 = __ldcg((const uint4*)&rh[(c + 1) * 32 + sw * 4 + 16]);
            pl0 = __ldcg((const uint4*)&rl[(c + 1) * 32 + sw * 4]);
            pl1 = __ldcg((const uint4*)&rl[(c + 1) * 32 + sw * 4 + 16]);
        }
        asm volatile("bar.sync %0, 64;" :: "r"(bid) : "memory");
        #pragma unroll
        for (int s = 0; s < 4; s++) {
            int o = 8 * s;
            u32 ah0 = Ah[ra0 + o], ah1 = Ah[ra1 + o], ah2 = Ah[ra0 + o + 4], ah3 = Ah[ra1 + o + 4];
            u32 al0 = Al[ra0 + o], al1 = Al[ra1 + o], al2 = Al[ra0 + o + 4], al3 = Al[ra1 + o + 4];
            const u32* bh = Whi + (c * 32 + o + t4) * WP + n0 + g;
            const u32* bl = Wlo + (c * 32 + o + t4) * WP + n0 + g;
            u32 b0h[4], b1h[4], b0l[4], b1l[4];
            #pragma unroll
            for (int nb = 0; nb < 4; nb++) {
                b0h[nb] = bh[8 * nb]; b1h[nb] = bh[8 * nb + 4 * WP];
                b0l[nb] = bl[8 * nb]; b1l[nb] = bl[8 * nb + 4 * WP];
            }
            #pragma unroll
            for (int nb = 0; nb < 4; nb++)
                mma16(acc[nb], ah0, ah1, ah2, ah3, b0h[nb], b1h[nb]);
            #pragma unroll
            for (int nb = 0; nb < 4; nb++)
                mma16(acc[nb], ah0, ah1, ah2, ah3, b0l[nb], b1l[nb]);
            #pragma unroll
            for (int nb = 0; nb < 4; nb++)
                mma16(acc[nb], al0, al1, al2, al3, b0h[nb], b1h[nb]);
        }
    }
}

// gather the 4 gates of a unit into one lane (cols packed unit*4+gate)
__device__ __forceinline__ float4 gather_gates(const float* a4, int rowSel) {
    float sx = rowSel ? a4[0] : a4[2];
    float sy = rowSel ? a4[1] : a4[3];
    float rx = __shfl_xor_sync(0xffffffffu, sx, 1);
    float ry = __shfl_xor_sync(0xffffffffu, sy, 1);
    return rowSel ? make_float4(rx, ry, a4[2], a4[3])
                  : make_float4(a4[0], a4[1], rx, ry);
}

// =================== persistent encoder =====================================
#define ENC_SMEM 122880
__global__ __launch_bounds__(256) void enc_persist(
    const float* __restrict__ data,
    const float* __restrict__ Wx_f, const float* __restrict__ Wh_f, const float* __restrict__ b_f,
    const float* __restrict__ Wx_b, const float* __restrict__ Wh_b, const float* __restrict__ b_b)
{
    extern __shared__ u32 sm[];
    u32*  Whi = sm;
    u32*  Wlo = sm + 9216;
    u32*  Ab  = sm + 18432;
    float* Wxs = (float*)(sm + 27648);
    float* Xsm = (float*)(sm + 27968);

    const int tid = threadIdx.x, lane = tid & 31, warp = tid >> 5;
    const int g = lane >> 2, t4 = lane & 3;
    const int m0 = (warp & 3) * 16, n0 = (warp >> 2) * 32;
    const int dir = blockIdx.x >> 6, bt = (blockIdx.x >> 4) & 3, ut = blockIdx.x & 15;
    const int b0 = bt * 64, u0 = ut * 16;

    const float* __restrict__ Wh = dir ? Wh_b : Wh_f;
    const float* __restrict__ Wx = dir ? Wx_b : Wx_f;
    const float* __restrict__ bb = dir ? b_b  : b_f;
    u32* hH[2] = { dir ? g_hbH[0] : g_hfH[0], dir ? g_hbH[1] : g_hfH[1] };
    u32* hL[2] = { dir ? g_hbL[0] : g_hfL[0], dir ? g_hbL[1] : g_hfL[1] };
    int* fbase  = g_pflag + (dir * 4 + bt) * 16;
    int* done   = &g_done[dir * 4 + bt];

    for (int i = tid; i < 8192; i += 256) {
        int kp = i >> 6, c = i & 63, ul = c >> 2, gate = c & 3;
        float w0 = __ldg(&Wh[(2 * kp)     * 1024 + gate * Hn + u0 + ul]);
        float w1 = __ldg(&Wh[(2 * kp + 1) * 1024 + gate * Hn + u0 + ul]);
        u32 lo, hi = pack_hi(w0, w1, lo);
        Whi[kp * WP + c] = hi; Wlo[kp * WP + c] = lo;
    }
    for (int i = tid; i < 320; i += 256) {
        int j = i >> 6, c = i & 63, ul = c >> 2, gate = c & 3;
        Wxs[i] = __ldg(&Wx[j * 1024 + gate * Hn + u0 + ul]);
    }

    const int rowSel = t4 & 1;
    const int upart  = t4 >> 1;
    const int myrow  = m0 + g + 8 * rowSel;
    const int nhalf  = n0 >> 5;
    const int srow = ((warp & 3) << 4) + ((warp >> 2) << 3) + (lane >> 2);
    const int sw = lane & 3;
    const int ra0 = (m0 + g) * AP + t4, ra1 = (m0 + g + 8) * AP + t4;

    float4 bsv[4];
    #pragma unroll
    for (int nb = 0; nb < 4; nb++) {
        int u = u0 + 8 * nhalf + 2 * nb + upart;
        bsv[nb] = make_float4(__ldg(&bb[u]), __ldg(&bb[Hn + u]),
                              __ldg(&bb[2 * Hn + u]), __ldg(&bb[3 * Hn + u]));
    }
    float creg[4] = {0, 0, 0, 0};

    if (tid < 64) {
        int xtime = dir ? Tn : 1;
        #pragma unroll
        for (int j = 0; j < 5; j++)
            Xsm[tid * 5 + j] = __ldg(&data[(size_t)(b0 + tid) * 1255 + xtime * 5 + j]);
    }
    __syncthreads();

    for (int t = 0; t < Tn; t++) {
        const u32* hiIn = hH[t & 1]; const u32* loIn = hL[t & 1];
        u32* hiOut = hH[(t + 1) & 1]; u32* loOut = hL[(t + 1) & 1];

        float acc[4][4] = {};
        if (t > 0) {
            wait_all(fbase, 16, t);
            mma_steps<4>(acc, &hiIn[(size_t)(b0 + srow) * 128], &loIn[(size_t)(b0 + srow) * 128],
                         Ab, Whi, Wlo, srow, sw, ra0, ra1, n0, g, t4);
        }

        const float* xr = &Xsm[(t & 1) * 320 + myrow * 5];
        float x0 = xr[0], x1 = xr[1], x2 = xr[2], x3 = xr[3], x4 = xr[4];
        u32 hiw[4], low[4];
        #pragma unroll
        for (int nb = 0; nb < 4; nb++) {
            float4 p = gather_gates(acc[nb], rowSel);
            int uc = 8 * nhalf + 2 * nb + upart;
            p.x += bsv[nb].x; p.y += bsv[nb].y; p.z += bsv[nb].z; p.w += bsv[nb].w;
            const float* wx = &Wxs[4 * uc];
            p.x = fmaf(x0, wx[0], p.x); p.y = fmaf(x0, wx[1], p.y);
            p.z = fmaf(x0, wx[2], p.z); p.w = fmaf(x0, wx[3], p.w);
            p.x = fmaf(x1, wx[64], p.x); p.y = fmaf(x1, wx[65], p.y);
            p.z = fmaf(x1, wx[66], p.z); p.w = fmaf(x1, wx[67], p.w);
            p.x = fmaf(x2, wx[128], p.x); p.y = fmaf(x2, wx[129], p.y);
            p.z = fmaf(x2, wx[130], p.z); p.w = fmaf(x2, wx[131], p.w);
            p.x = fmaf(x3, wx[192], p.x); p.y = fmaf(x3, wx[193], p.y);
            p.z = fmaf(x3, wx[194], p.z); p.w = fmaf(x3, wx[195], p.w);
            p.x = fmaf(x4, wx[256], p.x); p.y = fmaf(x4, wx[257], p.y);
            p.z = fmaf(x4, wx[258], p.z); p.w = fmaf(x4, wx[259], p.w);
            float cn = sigf(p.y) * creg[nb] + sigf(p.x) * tanha(p.z);
            float h = sigf(p.w) * tanha(cn);
            creg[nb] = cn;
            __nv_bfloat16 hb = __float2bfloat16_rn(h);
            __nv_bfloat16 lb = __float2bfloat16_rn(h - __bfloat162float(hb));
            u32 hl = (u32)*(u16*)&hb | ((u32)*(u16*)&lb << 16);
            u32 pr = __shfl_xor_sync(0xffffffffu, hl, 2);
            hiw[nb] = (hl & 0xFFFFu) | ((pr & 0xFFFFu) << 16);
            low[nb] = (hl >> 16) | (pr & 0xFFFF0000u);
        }
        if (upart == 0) {
            size_t base = (size_t)(b0 + myrow) * 128 + ut * 8 + 4 * nhalf;
            __stcg((uint4*)&hiOut[base], make_uint4(hiw[0], hiw[1], hiw[2], hiw[3]));
            __stcg((uint4*)&loOut[base], make_uint4(low[0], low[1], low[2], low[3]));
        }
        if (tid < 64 && t + 1 < Tn) {
            int xtime = dir ? (Tn - t - 1) : (t + 2);
            #pragma unroll
            for (int j = 0; j < 5; j++)
                Xsm[((t + 1) & 1) * 320 + tid * 5 + j] =
                    __ldg(&data[(size_t)(b0 + tid) * 1255 + xtime * 5 + j]);
        }
        __syncthreads();
        if (tid == 0 && t < Tn - 1) red_rel(fbase + ut);
    }
    if (tid == 0) {
        int old = atomicAdd(done, 1);
        if (old == 15) {
            for (int j = 0; j < 16; j++) atomicExch(fbase + j, 0);
            atomicExch(done, 0);
        }
    }
}

// =================== persistent decoder =====================================
#define DEC_SMEM 188160
__global__ __launch_bounds__(256) void dec_persist(
    const float* __restrict__ data,
    const float* __restrict__ dec_Wx, const float* __restrict__ Wh)
{
    extern __shared__ u32 sm[];
    u32*  Whi = sm;
    u32*  Wlo = sm + 18432;
    u32*  Ab  = sm + 36864;
    float* Wxs = (float*)(sm + 46080);
    float* Xsm = (float*)(sm + 46400);

    const int tid = threadIdx.x, lane = tid & 31, warp = tid >> 5;
    const int g = lane >> 2, t4 = lane & 3;
    const int m0 = (warp & 3) * 16, n0 = (warp >> 2) * 32;
    const int bt = blockIdx.x >> 5, ut = blockIdx.x & 31;
    const int b0 = bt * 64, u0 = ut * 16;
    int* fbase = g_pflag + 128 + bt * 32;
    int* done  = &g_done[8 + bt];

    for (int i = tid; i < 16384; i += 256) {
        int kp = i >> 6, c = i & 63, ul = c >> 2, gate = c & 3;
        float w0 = __ldg(&Wh[(2 * kp)     * 2048 + gate * Dn + u0 + ul]);
        float w1 = __ldg(&Wh[(2 * kp + 1) * 2048 + gate * Dn + u0 + ul]);
        u32 lo, hi = pack_hi(w0, w1, lo);
        Whi[kp * WP + c] = hi; Wlo[kp * WP + c] = lo;
    }
    for (int i = tid; i < 320; i += 256) {
        int j = i >> 6, c = i & 63, ul = c >> 2, gate = c & 3;
        Wxs[i] = __ldg(&dec_Wx[j * 2048 + gate * Dn + u0 + ul]);
    }

    const int rowSel = t4 & 1;
    const int upart  = t4 >> 1;
    const int myrow  = m0 + g + 8 * rowSel;
    const int nhalf  = n0 >> 5;
    const int srow = ((warp & 3) << 4) + ((warp >> 2) << 3) + (lane >> 2);
    const int sw = lane & 3;
    const int ra0 = (m0 + g) * AP + t4, ra1 = (m0 + g + 8) * AP + t4;

    float4 zgv[4]; float creg[4];
    #pragma unroll
    for (int nb = 0; nb < 4; nb++) {
        int u = u0 + 8 * nhalf + 2 * nb + upart;
        int b = b0 + myrow;
        zgv[nb] = make_float4(g_zgT[((size_t)0 * Dn + u) * Bn + b],
                              g_zgT[((size_t)1 * Dn + u) * Bn + b],
                              g_zgT[((size_t)2 * Dn + u) * Bn + b],
                              g_zgT[((size_t)3 * Dn + u) * Bn + b]);
        creg[nb] = g_cdT[(size_t)u * Bn + b];
    }

    if (tid < 64) {
        #pragma unroll
        for (int j = 0; j < 5; j++)
            Xsm[tid * 5 + j] = __ldg(&data[(size_t)(b0 + tid) * 1255 + 0 * 5 + j]);
    }
    __syncthreads();

    for (int t = 0; t < Tn; t++) {
        const u32* hiIn = g_hdH[t & 1]; const u32* loIn = g_hdL[t & 1];
        u32* hiOut = g_hdH[(t + 1) & 1]; u32* loOut = g_hdL[(t + 1) & 1];

        float acc[4][4] = {};
        wait_all(fbase, 32, t);
        mma_steps<8>(acc, &hiIn[(size_t)(b0 + srow) * 256], &loIn[(size_t)(b0 + srow) * 256],
                     Ab, Whi, Wlo, srow, sw, ra0, ra1, n0, g, t4);

        const float* xr = &Xsm[(t & 1) * 320 + myrow * 5];
        float x0 = xr[0], x1 = xr[1], x2 = xr[2], x3 = xr[3], x4 = xr[4];
        u32 hiw[4], low[4];
        #pragma unroll
        for (int nb = 0; nb < 4; nb++) {
            float4 p = gather_gates(acc[nb], rowSel);
            int uc = 8 * nhalf + 2 * nb + upart;
            p.x += zgv[nb].x; p.y += zgv[nb].y; p.z += zgv[nb].z; p.w += zgv[nb].w;
            const float* wx = &Wxs[4 * uc];
            p.x = fmaf(x0, wx[0], p.x); p.y = fmaf(x0, wx[1], p.y);
            p.z = fmaf(x0, wx[2], p.z); p.w = fmaf(x0, wx[3], p.w);
            p.x = fmaf(x1, wx[64], p.x); p.y = fmaf(x1, wx[65], p.y);
            p.z = fmaf(x1, wx[66], p.z); p.w = fmaf(x1, wx[67], p.w);
            p.x = fmaf(x2, wx[128], p.x); p.y = fmaf(x2, wx[129], p.y);
            p.z = fmaf(x2, wx[130], p.z); p.w = fmaf(x2, wx[131], p.w);
            p.x = fmaf(x3, wx[192], p.x); p.y = fmaf(x3, wx[193], p.y);
            p.z = fmaf(x3, wx[194], p.z); p.w = fmaf(x3, wx[195], p.w);
            p.x = fmaf(x4, wx[256], p.x); p.y = fmaf(x4, wx[257], p.y);
            p.z = fmaf(x4, wx[258], p.z); p.w = fmaf(x4, wx[259], p.w);
            float cn = sigf(p.y) * creg[nb] + sigf(p.x) * tanha(p.z);
            float h = sigf(p.w) * tanha(cn);
            creg[nb] = cn;
            __nv_bfloat16 hb = __float2bfloat16_rn(h);
            __nv_bfloat16 lb = __float2bfloat16_rn(h - __bfloat162float(hb));
            u32 hl = (u32)*(u16*)&hb | ((u32)*(u16*)&lb << 16);
            u32 pr = __shfl_xor_sync(0xffffffffu, hl, 2);
            hiw[nb] = (hl & 0xFFFFu) | ((pr & 0xFFFFu) << 16);
            low[nb] = (hl >> 16) | (pr & 0xFFFF0000u);
        }
        if (upart == 0) {
            size_t base = (size_t)(b0 + myrow) * 256 + ut * 8 + 4 * nhalf;
            uint4 hv = make_uint4(hiw[0], hiw[1], hiw[2], hiw[3]);
            uint4 lv = make_uint4(low[0], low[1], low[2], low[3]);
            __stcg((uint4*)&hiOut[base], hv);
            __stcg((uint4*)&loOut[base], lv);
            size_t hb2 = ((size_t)t * Bn + b0 + myrow) * 256 + ut * 8 + 4 * nhalf;
            __stcg((uint4*)&g_hsH[hb2], hv);
            __stcg((uint4*)&g_hsL[hb2], lv);
        }
        if (tid < 64 && t + 1 < Tn) {
            #pragma unroll
            for (int j = 0; j < 5; j++)
                Xsm[((t + 1) & 1) * 320 + tid * 5 + j] =
                    __ldg(&data[(size_t)(b0 + tid) * 1255 + (t + 1) * 5 + j]);
        }
        __syncthreads();
        if (tid == 0 && t < Tn - 1) red_rel(fbase + ut);
    }
    if (tid == 0) {
        int old = atomicAdd(done, 1);
        if (old == 31) {
            for (int j = 0; j < 32; j++) atomicExch(fbase + j, 0);
            atomicExch(done, 0);
        }
    }
}

// =================== latent stages ==========================================
__global__ void latent1(const float* __restrict__ W, const float* __restrict__ bias,
                        const float* __restrict__ eps,
                        float* __restrict__ zm, float* __restrict__ zl)
{
    int b = blockIdx.x, j = threadIdx.x;
    const __nv_bfloat16* fh = (const __nv_bfloat16*)g_hfH[0];
    const __nv_bfloat16* fl = (const __nv_bfloat16*)g_hfL[0];
    const __nv_bfloat16* bh = (const __nv_bfloat16*)g_hbH[0];
    const __nv_bfloat16* bl = (const __nv_bfloat16*)g_hbL[0];
    float sm = bias[j], sl = bias[j + Zn];
    for (int k = 0; k < Hn; k++) {
        float a = __bfloat162float(fh[b * Hn + k]) + __bfloat162float(fl[b * Hn + k]);
        sm = fmaf(a, W[k * (2 * Zn) + j], sm);
        sl = fmaf(a, W[k * (2 * Zn) + Zn + j], sl);
    }
    for (int k = 0; k < Hn; k++) {
        float a = __bfloat162float(bh[b * Hn + k]) + __bfloat162float(bl[b * Hn + k]);
        sm = fmaf(a, W[(Hn + k) * (2 * Zn) + j], sm);
        sl = fmaf(a, W[(Hn + k) * (2 * Zn) + Zn + j], sl);
    }
    zm[b * Zn + j] = sm;
    zl[b * Zn + j] = sl;
    g_z[b * Zn + j] = sm + expf(0.5f * sl) * eps[b * Zn + j];
}

__global__ __launch_bounds__(256) void latent2(
    const float* __restrict__ init_W, const float* __restrict__ init_b,
    const float* __restrict__ dec_Wx, const float* __restrict__ dec_b)
{
    __shared__ float zs[32][Zn];
    const int tid = threadIdx.x;
    const int tx = tid & 31, ty = tid >> 5;
    const int b0 = blockIdx.x * 32;
    const int col0 = blockIdx.y * 128;
    const bool isInit = (col0 < 2 * Dn);

    for (int i = tid; i < 32 * Zn; i += 256)
        zs[i >> 7][i & 127] = g_z[(b0 + (i >> 7)) * Zn + (i & 127)];
    __syncthreads();

    const int col = col0 + tx * 4;
    const float* Wcol = isInit ? (init_W + col) : (dec_Wx + 5 * (4 * Dn) + (col - 2 * Dn));
    const int wstride = isInit ? (2 * Dn) : (4 * Dn);

    float acc[4][4] = {};
    #pragma unroll 4
    for (int k = 0; k < Zn; k++) {
        float4 w = *(const float4*)&Wcol[k * wstride];
        float a0 = zs[ty * 4 + 0][k], a1 = zs[ty * 4 + 1][k];
        float a2 = zs[ty * 4 + 2][k], a3 = zs[ty * 4 + 3][k];
        acc[0][0] = fmaf(a0, w.x, acc[0][0]); acc[0][1] = fmaf(a0, w.y, acc[0][1]);
        acc[0][2] = fmaf(a0, w.z, acc[0][2]); acc[0][3] = fmaf(a0, w.w, acc[0][3]);
        acc[1][0] = fmaf(a1, w.x, acc[1][0]); acc[1][1] = fmaf(a1, w.y, acc[1][1]);
        acc[1][2] = fmaf(a1, w.z, acc[1][2]); acc[1][3] = fmaf(a1, w.w, acc[1][3]);
        acc[2][0] = fmaf(a2, w.x, acc[2][0]); acc[2][1] = fmaf(a2, w.y, acc[2][1]);
        acc[2][2] = fmaf(a2, w.z, acc[2][2]); acc[2][3] = fmaf(a2, w.w, acc[2][3]);
        acc[3][0] = fmaf(a3, w.x, acc[3][0]); acc[3][1] = fmaf(a3, w.y, acc[3][1]);
        acc[3][2] = fmaf(a3, w.z, acc[3][2]); acc[3][3] = fmaf(a3, w.w, acc[3][3]);
    }

    __nv_bfloat16* hH = (__nv_bfloat16*)g_hdH[0];
    __nv_bfloat16* hL = (__nv_bfloat16*)g_hdL[0];
    #pragma unroll
    for (int r = 0; r < 4; r++) {
        int b = b0 + ty * 4 + r;
        #pragma unroll
        for (int c = 0; c < 4; c++) {
            int cc = col + c;
            if (isInit) {
                float v = tanhf(acc[r][c] + init_b[cc]);
                if (cc < Dn) {
                    __nv_bfloat16 hb = __float2bfloat16_rn(v);
                    hH[(size_t)b * Dn + cc] = hb;
                    hL[(size_t)b * Dn + cc] = __float2bfloat16_rn(v - __bfloat162float(hb));
                } else {
                    g_cdT[(size_t)(cc - Dn) * Bn + b] = v;
                }
            } else {
                int c2 = cc - 2 * Dn;
                g_zgT[(size_t)c2 * Bn + b] = acc[r][c] + dec_b[c2];
            }
        }
    }
}

// =================== mix weight prepack =====================================
__global__ void pack_mix(const float* __restrict__ Wm) {
    int i = blockIdx.x * 256 + threadIdx.x;   // 32768 total
    int kp = i >> 7, c = i & 127;
    float w0 = (c < Pn) ? __ldg(&Wm[(2 * kp)     * Pn + c]) : 0.f;
    float w1 = (c < Pn) ? __ldg(&Wm[(2 * kp + 1) * Pn + c]) : 0.f;
    u32 lo, hi = pack_hi(w0, w1, lo);
    g_WmH[kp * 128 + c] = hi;
    g_WmL[kp * 128 + c] = lo;
}

// =================== output head: tensor-core GEMM, prepacked W =============
#define MIX_SMEM 201728
__global__ __launch_bounds__(256) void mix_mma(
    const float* __restrict__ bm, float* __restrict__ out)
{
    extern __shared__ u32 sm[];
    u32*  Whi = sm;                     // [256 kp][72]
    u32*  Wlo = sm + 18432;
    u32*  Ab  = sm + 36864;             // 4 x 2304
    float* Csm = (float*)(sm + 46080);  // [64][68]

    const int tid = threadIdx.x, lane = tid & 31, warp = tid >> 5;
    const int g = lane >> 2, t4 = lane & 3;
    const int m0 = (warp & 3) * 16, n0 = (warp >> 2) * 32;
    const int row0 = blockIdx.x * 64;
    const int col0 = blockIdx.y * 64;

    // coalesced fill from prepacked W (no conversion math)
    for (int i = tid; i < 16384; i += 256) {
        int kp = i >> 6, c = i & 63;
        Whi[kp * WP + c] = g_WmH[kp * 128 + col0 + c];
        Wlo[kp * WP + c] = g_WmL[kp * 128 + col0 + c];
    }
    __syncthreads();

    const int srow = ((warp & 3) << 4) + ((warp >> 2) << 3) + (lane >> 2);
    const int sw = lane & 3;
    const int ra0 = (m0 + g) * AP + t4, ra1 = (m0 + g + 8) * AP + t4;
    float acc[4][4] = {};
    mma_steps<8>(acc, &g_hsH[(size_t)(row0 + srow) * 256], &g_hsL[(size_t)(row0 + srow) * 256],
                 Ab, Whi, Wlo, srow, sw, ra0, ra1, n0, g, t4);

    #pragma unroll
    for (int nb = 0; nb < 4; nb++) {
        int colp = n0 + 8 * nb + 2 * t4;
        *(float2*)&Csm[(m0 + g) * 68 + colp]     = make_float2(acc[nb][0], acc[nb][1]);
        *(float2*)&Csm[(m0 + g + 8) * 68 + colp] = make_float2(acc[nb][2], acc[nb][3]);
    }
    __syncthreads();

    if (tid < 64) {
        int grow = row0 + tid;             // = t*Bn + b
        int tt = grow >> 8, bb2 = grow & 255;
        float* o = out + ((size_t)bb2 * Tn + tt) * Pn;
        const float* yr = &Csm[tid * 68];
        if (col0 == 0) {
            float e[Kn]; float m = -1e30f;
            #pragma unroll
            for (int j = 0; j < Kn; j++) { e[j] = yr[j] + __ldg(&bm[j]); m = fmaxf(m, e[j]); }
            float s = 0.f;
            #pragma unroll
            for (int j = 0; j < Kn; j++) { e[j] = expf(e[j] - m); s += e[j]; }
            float inv = 1.0f / s;
            #pragma unroll
            for (int j = 0; j < Kn; j++) o[j] = e[j] * inv;                    // pi
            for (int c = 20; c < 60; c++) o[c] = yr[c] + __ldg(&bm[c]);        // mu
            for (int c = 60; c < 64; c++) o[c] = expf(yr[c] + __ldg(&bm[c]));  // sigma head
        } else {
            for (int c = 0; c < 59; c++) {
                int col = 64 + c;
                float v = yr[c] + __ldg(&bm[col]);
                if (col < 100)      v = expf(v);     // sigma
                else if (col < 120) v = tanhf(v);    // rho
                o[col] = v;                          // pen = copy
            }
        }
    }
}

// =================== launcher ================================================
extern "C" void kernel_launch(void* const* d_in, const int* in_sizes, int n_in,
                              void* d_out, int out_size)
{
    (void)in_sizes; (void)n_in; (void)out_size;
    const float* data      = (const float*)d_in[0];
    const float* eps       = (const float*)d_in[1];
    const float* enc_Wx_f  = (const float*)d_in[2];
    const float* enc_Wh_f  = (const float*)d_in[3];
    const float* enc_b_f   = (const float*)d_in[4];
    const float* enc_Wx_b  = (const float*)d_in[5];
    const float* enc_Wh_b  = (const float*)d_in[6];
    const float* enc_b_b   = (const float*)d_in[7];
    const float* enc_out_W = (const float*)d_in[8];
    const float* enc_out_b = (const float*)d_in[9];
    const float* init_W    = (const float*)d_in[10];
    const float* init_b    = (const float*)d_in[11];
    const float* dec_Wx    = (const float*)d_in[12];
    const float* dec_Wh    = (const float*)d_in[13];
    const float* dec_b     = (const float*)d_in[14];
    const float* mix_W     = (const float*)d_in[15];
    const float* mix_b     = (const float*)d_in[16];
    float* out = (float*)d_out;

    cudaFuncSetAttribute(enc_persist, cudaFuncAttributeMaxDynamicSharedMemorySize, ENC_SMEM);
    cudaFuncSetAttribute(dec_persist, cudaFuncAttributeMaxDynamicSharedMemorySize, DEC_SMEM);
    cudaFuncSetAttribute(mix_mma,     cudaFuncAttributeMaxDynamicSharedMemorySize, MIX_SMEM);

    const size_t params_sz = (size_t)Bn * Tn * Pn;

    pack_mix<<<128, 256>>>(mix_W);
    enc_persist<<<128, 256, ENC_SMEM>>>(data, enc_Wx_f, enc_Wh_f, enc_b_f,
                                        enc_Wx_b, enc_Wh_b, enc_b_b);
    latent1<<<Bn, 128>>>(enc_out_W, enc_out_b, eps,
                         out + params_sz, out + params_sz + (size_t)Bn * Zn);
    latent2<<<dim3(8, 24), 256>>>(init_W, init_b, dec_Wx, dec_b);
    dec_persist<<<128, 256, DEC_SMEM>>>(data, dec_Wx, dec_Wh);
    mix_mma<<<dim3(TB / 64, 2), 256, MIX_SMEM>>>(mix_b, out);
}

// round 17
// speedup vs baseline: 1.2721x; 1.0079x over previous
#include <cuda_runtime.h>
#include <cuda_bf16.h>
#include <math.h>

#define Bn 256
#define Tn 250
#define Zn 128
#define Hn 256
#define Dn 512
#define Kn 20
#define Pn 123
#define TB (Tn*Bn)

typedef unsigned long long ull;
typedef unsigned int u32;
typedef unsigned short u16;

__device__ u32  g_hfH[2][Bn*Hn/2];
__device__ u32  g_hfL[2][Bn*Hn/2];
__device__ u32  g_hbH[2][Bn*Hn/2];
__device__ u32  g_hbL[2][Bn*Hn/2];
__device__ u32  g_hdH[2][Bn*Dn/2];
__device__ u32  g_hdL[2][Bn*Dn/2];
__device__ u32  g_hsH[(size_t)TB*(Dn/2)];
__device__ u32  g_hsL[(size_t)TB*(Dn/2)];
__device__ u32  g_WmH[256*128];
__device__ u32  g_WmL[256*128];
__device__ float g_z  [Bn*Zn];
__device__ float g_zgT[4*Dn*Bn];
__device__ float g_cdT[Dn*Bn];
__device__ int   g_cnt[16];      // per-group warp-arrival counters
__device__ int   g_done[16];

// ---- fast transcendentals ----
__device__ __forceinline__ float ex2a(float x){ float y; asm("ex2.approx.f32 %0,%1;":"=f"(y):"f"(x)); return y; }
__device__ __forceinline__ float rcpa(float x){ float y; asm("rcp.approx.f32 %0,%1;":"=f"(y):"f"(x)); return y; }
__device__ __forceinline__ float sigf(float x){ return rcpa(1.0f + ex2a(-1.4426950408889634f * x)); }
__device__ __forceinline__ float tanha(float x){ return 1.0f - 2.0f * rcpa(ex2a(2.8853900817779268f * x) + 1.0f); }

__device__ __forceinline__ int ld_acq(const int* p) {
    int v; asm volatile("ld.acquire.gpu.global.s32 %0, [%1];" : "=r"(v) : "l"(p) : "memory");
    return v;
}
__device__ __forceinline__ void red_rel(int* p) {
    asm volatile("red.release.gpu.global.add.s32 [%0], 1;" :: "l"(p) : "memory");
}
__device__ __forceinline__ void wait_cnt(const int* ctr, int target) {
    if ((threadIdx.x & 31) == 0) { while (ld_acq(ctr) < target) { } }
    __syncwarp();
}
__device__ __forceinline__ u32 pack_hi(float a, float b, u32& lo) {
    __nv_bfloat16 ha = __float2bfloat16_rn(a), hb = __float2bfloat16_rn(b);
    __nv_bfloat16 la = __float2bfloat16_rn(a - __bfloat162float(ha));
    __nv_bfloat16 lb = __float2bfloat16_rn(b - __bfloat162float(hb));
    __nv_bfloat162 ph(ha, hb), pl(la, lb);
    lo = *(u32*)&pl;
    return *(u32*)&ph;
}
__device__ __forceinline__ void mma16(float* c, u32 a0, u32 a1, u32 a2, u32 a3,
                                      u32 b0, u32 b1) {
    asm("mma.sync.aligned.m16n8k16.row.col.f32.bf16.bf16.f32 "
        "{%0,%1,%2,%3}, {%4,%5,%6,%7}, {%8,%9}, {%0,%1,%2,%3};"
        : "+f"(c[0]), "+f"(c[1]), "+f"(c[2]), "+f"(c[3])
        : "r"(a0), "r"(a1), "r"(a2), "r"(a3), "r"(b0), "r"(b1));
}

#define WP 72
#define AP 36

// Pair-local staging + named pair barriers. TERM-MAJOR inner loop.
template<int CN>
__device__ __forceinline__ void mma_steps(
    float (&acc)[4][4], const u32* rh, const u32* rl,
    u32* Ab, const u32* Whi, const u32* Wlo,
    int srow, int sw, int ra0, int ra1, int n0, int g, int t4)
{
    const int bid = 1 + ((threadIdx.x >> 5) & 3);
    uint4 ph0, ph1, pl0, pl1;
    ph0 = __ldcg((const uint4*)&rh[sw * 4]);  ph1 = __ldcg((const uint4*)&rh[sw * 4 + 16]);
    pl0 = __ldcg((const uint4*)&rl[sw * 4]);  pl1 = __ldcg((const uint4*)&rl[sw * 4 + 16]);
    #pragma unroll 1
    for (int c = 0; c < CN; c++) {
        u32* Ah = Ab + (c & 1) * 2304;
        u32* Al = Ab + 4608 + (c & 1) * 2304;
        *(uint4*)&Ah[srow * AP + sw * 4]      = ph0;
        *(uint4*)&Ah[srow * AP + sw * 4 + 16] = ph1;
        *(uint4*)&Al[srow * AP + sw * 4]      = pl0;
        *(uint4*)&Al[srow * AP + sw * 4 + 16] = pl1;
        if (c < CN - 1) {
            ph0 = __ldcg((const uint4*)&rh[(c + 1) * 32 + sw * 4]);
            ph1 = __ldcg((const uint4*)&rh[(c + 1) * 32 + sw * 4 + 16]);
            pl0 = __ldcg((const uint4*)&rl[(c + 1) * 32 + sw * 4]);
            pl1 = __ldcg((const uint4*)&rl[(c + 1) * 32 + sw * 4 + 16]);
        }
        asm volatile("bar.sync %0, 64;" :: "r"(bid) : "memory");
        #pragma unroll
        for (int s = 0; s < 4; s++) {
            int o = 8 * s;
            u32 ah0 = Ah[ra0 + o], ah1 = Ah[ra1 + o], ah2 = Ah[ra0 + o + 4], ah3 = Ah[ra1 + o + 4];
            u32 al0 = Al[ra0 + o], al1 = Al[ra1 + o], al2 = Al[ra0 + o + 4], al3 = Al[ra1 + o + 4];
            const u32* bh = Whi + (c * 32 + o + t4) * WP + n0 + g;
            const u32* bl = Wlo + (c * 32 + o + t4) * WP + n0 + g;
            u32 b0h[4], b1h[4], b0l[4], b1l[4];
            #pragma unroll
            for (int nb = 0; nb < 4; nb++) {
                b0h[nb] = bh[8 * nb]; b1h[nb] = bh[8 * nb + 4 * WP];
                b0l[nb] = bl[8 * nb]; b1l[nb] = bl[8 * nb + 4 * WP];
            }
            #pragma unroll
            for (int nb = 0; nb < 4; nb++)
                mma16(acc[nb], ah0, ah1, ah2, ah3, b0h[nb], b1h[nb]);
            #pragma unroll
            for (int nb = 0; nb < 4; nb++)
                mma16(acc[nb], ah0, ah1, ah2, ah3, b0l[nb], b1l[nb]);
            #pragma unroll
            for (int nb = 0; nb < 4; nb++)
                mma16(acc[nb], al0, al1, al2, al3, b0h[nb], b1h[nb]);
        }
    }
}

__device__ __forceinline__ float4 gather_gates(const float* a4, int rowSel) {
    float sx = rowSel ? a4[0] : a4[2];
    float sy = rowSel ? a4[1] : a4[3];
    float rx = __shfl_xor_sync(0xffffffffu, sx, 1);
    float ry = __shfl_xor_sync(0xffffffffu, sy, 1);
    return rowSel ? make_float4(rx, ry, a4[2], a4[3])
                  : make_float4(a4[0], a4[1], rx, ry);
}

// =================== persistent encoder =====================================
#define ENC_SMEM 122880
__global__ __launch_bounds__(256) void enc_persist(
    const float* __restrict__ data,
    const float* __restrict__ Wx_f, const float* __restrict__ Wh_f, const float* __restrict__ b_f,
    const float* __restrict__ Wx_b, const float* __restrict__ Wh_b, const float* __restrict__ b_b)
{
    extern __shared__ u32 sm[];
    u32*  Whi = sm;
    u32*  Wlo = sm + 9216;
    u32*  Ab  = sm + 18432;
    float* Wxs = (float*)(sm + 27648);

    const int tid = threadIdx.x, lane = tid & 31, warp = tid >> 5;
    const int g = lane >> 2, t4 = lane & 3;
    const int m0 = (warp & 3) * 16, n0 = (warp >> 2) * 32;
    const int dir = blockIdx.x >> 6, bt = (blockIdx.x >> 4) & 3, ut = blockIdx.x & 15;
    const int b0 = bt * 64, u0 = ut * 16;

    const float* __restrict__ Wh = dir ? Wh_b : Wh_f;
    const float* __restrict__ Wx = dir ? Wx_b : Wx_f;
    const float* __restrict__ bb = dir ? b_b  : b_f;
    u32* hH[2] = { dir ? g_hbH[0] : g_hfH[0], dir ? g_hbH[1] : g_hfH[1] };
    u32* hL[2] = { dir ? g_hbL[0] : g_hfL[0], dir ? g_hbL[1] : g_hfL[1] };
    int* ctr  = &g_cnt[dir * 4 + bt];
    int* done = &g_done[dir * 4 + bt];

    for (int i = tid; i < 8192; i += 256) {
        int kp = i >> 6, c = i & 63, ul = c >> 2, gate = c & 3;
        float w0 = __ldg(&Wh[(2 * kp)     * 1024 + gate * Hn + u0 + ul]);
        float w1 = __ldg(&Wh[(2 * kp + 1) * 1024 + gate * Hn + u0 + ul]);
        u32 lo, hi = pack_hi(w0, w1, lo);
        Whi[kp * WP + c] = hi; Wlo[kp * WP + c] = lo;
    }
    for (int i = tid; i < 320; i += 256) {
        int j = i >> 6, c = i & 63, ul = c >> 2, gate = c & 3;
        Wxs[i] = __ldg(&Wx[j * 1024 + gate * Hn + u0 + ul]);
    }

    const int rowSel = t4 & 1;
    const int upart  = t4 >> 1;
    const int myrow  = m0 + g + 8 * rowSel;
    const int nhalf  = n0 >> 5;
    const int srow = ((warp & 3) << 4) + ((warp >> 2) << 3) + (lane >> 2);
    const int sw = lane & 3;
    const int ra0 = (m0 + g) * AP + t4, ra1 = (m0 + g + 8) * AP + t4;

    float4 bsv[4];
    #pragma unroll
    for (int nb = 0; nb < 4; nb++) {
        int u = u0 + 8 * nhalf + 2 * nb + upart;
        bsv[nb] = make_float4(__ldg(&bb[u]), __ldg(&bb[Hn + u]),
                              __ldg(&bb[2 * Hn + u]), __ldg(&bb[3 * Hn + u]));
    }
    float creg[4] = {0, 0, 0, 0};
    __syncthreads();   // weights staged

    for (int t = 0; t < Tn; t++) {
        const u32* hiIn = hH[t & 1]; const u32* loIn = hL[t & 1];
        u32* hiOut = hH[(t + 1) & 1]; u32* loOut = hL[(t + 1) & 1];
        const int xtime = dir ? (Tn - t) : (t + 1);

        // per-lane x loads (L1-cached, off critical path)
        const float* xp = &data[(size_t)(b0 + myrow) * 1255 + xtime * 5];
        float x0 = __ldg(xp), x1 = __ldg(xp + 1), x2 = __ldg(xp + 2);
        float x3 = __ldg(xp + 3), x4 = __ldg(xp + 4);

        float acc[4][4] = {};
        if (t > 0) {
            wait_cnt(ctr, 128 * t);
            mma_steps<4>(acc, &hiIn[(size_t)(b0 + srow) * 128], &loIn[(size_t)(b0 + srow) * 128],
                         Ab, Whi, Wlo, srow, sw, ra0, ra1, n0, g, t4);
        }

        u32 hiw[4], low[4];
        #pragma unroll
        for (int nb = 0; nb < 4; nb++) {
            float4 p = gather_gates(acc[nb], rowSel);
            int uc = 8 * nhalf + 2 * nb + upart;
            p.x += bsv[nb].x; p.y += bsv[nb].y; p.z += bsv[nb].z; p.w += bsv[nb].w;
            const float* wx = &Wxs[4 * uc];
            p.x = fmaf(x0, wx[0], p.x); p.y = fmaf(x0, wx[1], p.y);
            p.z = fmaf(x0, wx[2], p.z); p.w = fmaf(x0, wx[3], p.w);
            p.x = fmaf(x1, wx[64], p.x); p.y = fmaf(x1, wx[65], p.y);
            p.z = fmaf(x1, wx[66], p.z); p.w = fmaf(x1, wx[67], p.w);
            p.x = fmaf(x2, wx[128], p.x); p.y = fmaf(x2, wx[129], p.y);
            p.z = fmaf(x2, wx[130], p.z); p.w = fmaf(x2, wx[131], p.w);
            p.x = fmaf(x3, wx[192], p.x); p.y = fmaf(x3, wx[193], p.y);
            p.z = fmaf(x3, wx[194], p.z); p.w = fmaf(x3, wx[195], p.w);
            p.x = fmaf(x4, wx[256], p.x); p.y = fmaf(x4, wx[257], p.y);
            p.z = fmaf(x4, wx[258], p.z); p.w = fmaf(x4, wx[259], p.w);
            float cn = sigf(p.y) * creg[nb] + sigf(p.x) * tanha(p.z);
            float h = sigf(p.w) * tanha(cn);
            creg[nb] = cn;
            __nv_bfloat16 hb = __float2bfloat16_rn(h);
            __nv_bfloat16 lb = __float2bfloat16_rn(h - __bfloat162float(hb));
            u32 hl = (u32)*(u16*)&hb | ((u32)*(u16*)&lb << 16);
            u32 pr = __shfl_xor_sync(0xffffffffu, hl, 2);
            hiw[nb] = (hl & 0xFFFFu) | ((pr & 0xFFFFu) << 16);
            low[nb] = (hl >> 16) | (pr & 0xFFFF0000u);
        }
        if (upart == 0) {
            size_t base = (size_t)(b0 + myrow) * 128 + ut * 8 + 4 * nhalf;
            __stcg((uint4*)&hiOut[base], make_uint4(hiw[0], hiw[1], hiw[2], hiw[3]));
            __stcg((uint4*)&loOut[base], make_uint4(low[0], low[1], low[2], low[3]));
        }
        // per-warp early release (no block sync on the handoff path)
        __syncwarp();
        if (lane == 0 && t < Tn - 1) red_rel(ctr);
    }
    if (tid == 0) {
        int old = atomicAdd(done, 1);
        if (old == 15) { atomicExch(ctr, 0); atomicExch(done, 0); }
    }
}

// =================== persistent decoder =====================================
#define DEC_SMEM 188160
__global__ __launch_bounds__(256) void dec_persist(
    const float* __restrict__ data,
    const float* __restrict__ dec_Wx, const float* __restrict__ Wh)
{
    extern __shared__ u32 sm[];
    u32*  Whi = sm;
    u32*  Wlo = sm + 18432;
    u32*  Ab  = sm + 36864;
    float* Wxs = (float*)(sm + 46080);

    const int tid = threadIdx.x, lane = tid & 31, warp = tid >> 5;
    const int g = lane >> 2, t4 = lane & 3;
    const int m0 = (warp & 3) * 16, n0 = (warp >> 2) * 32;
    const int bt = blockIdx.x >> 5, ut = blockIdx.x & 31;
    const int b0 = bt * 64, u0 = ut * 16;
    int* ctr  = &g_cnt[8 + bt];
    int* done = &g_done[8 + bt];

    for (int i = tid; i < 16384; i += 256) {
        int kp = i >> 6, c = i & 63, ul = c >> 2, gate = c & 3;
        float w0 = __ldg(&Wh[(2 * kp)     * 2048 + gate * Dn + u0 + ul]);
        float w1 = __ldg(&Wh[(2 * kp + 1) * 2048 + gate * Dn + u0 + ul]);
        u32 lo, hi = pack_hi(w0, w1, lo);
        Whi[kp * WP + c] = hi; Wlo[kp * WP + c] = lo;
    }
    for (int i = tid; i < 320; i += 256) {
        int j = i >> 6, c = i & 63, ul = c >> 2, gate = c & 3;
        Wxs[i] = __ldg(&dec_Wx[j * 2048 + gate * Dn + u0 + ul]);
    }

    const int rowSel = t4 & 1;
    const int upart  = t4 >> 1;
    const int myrow  = m0 + g + 8 * rowSel;
    const int nhalf  = n0 >> 5;
    const int srow = ((warp & 3) << 4) + ((warp >> 2) << 3) + (lane >> 2);
    const int sw = lane & 3;
    const int ra0 = (m0 + g) * AP + t4, ra1 = (m0 + g + 8) * AP + t4;

    float4 zgv[4]; float creg[4];
    #pragma unroll
    for (int nb = 0; nb < 4; nb++) {
        int u = u0 + 8 * nhalf + 2 * nb + upart;
        int b = b0 + myrow;
        zgv[nb] = make_float4(g_zgT[((size_t)0 * Dn + u) * Bn + b],
                              g_zgT[((size_t)1 * Dn + u) * Bn + b],
                              g_zgT[((size_t)2 * Dn + u) * Bn + b],
                              g_zgT[((size_t)3 * Dn + u) * Bn + b]);
        creg[nb] = g_cdT[(size_t)u * Bn + b];
    }
    __syncthreads();   // weights staged

    for (int t = 0; t < Tn; t++) {
        const u32* hiIn = g_hdH[t & 1]; const u32* loIn = g_hdL[t & 1];
        u32* hiOut = g_hdH[(t + 1) & 1]; u32* loOut = g_hdL[(t + 1) & 1];

        const float* xp = &data[(size_t)(b0 + myrow) * 1255 + t * 5];
        float x0 = __ldg(xp), x1 = __ldg(xp + 1), x2 = __ldg(xp + 2);
        float x3 = __ldg(xp + 3), x4 = __ldg(xp + 4);

        float acc[4][4] = {};
        wait_cnt(ctr, 256 * t);
        mma_steps<8>(acc, &hiIn[(size_t)(b0 + srow) * 256], &loIn[(size_t)(b0 + srow) * 256],
                     Ab, Whi, Wlo, srow, sw, ra0, ra1, n0, g, t4);

        u32 hiw[4], low[4];
        #pragma unroll
        for (int nb = 0; nb < 4; nb++) {
            float4 p = gather_gates(acc[nb], rowSel);
            int uc = 8 * nhalf + 2 * nb + upart;
            p.x += zgv[nb].x; p.y += zgv[nb].y; p.z += zgv[nb].z; p.w += zgv[nb].w;
            const float* wx = &Wxs[4 * uc];
            p.x = fmaf(x0, wx[0], p.x); p.y = fmaf(x0, wx[1], p.y);
            p.z = fmaf(x0, wx[2], p.z); p.w = fmaf(x0, wx[3], p.w);
            p.x = fmaf(x1, wx[64], p.x); p.y = fmaf(x1, wx[65], p.y);
            p.z = fmaf(x1, wx[66], p.z); p.w = fmaf(x1, wx[67], p.w);
            p.x = fmaf(x2, wx[128], p.x); p.y = fmaf(x2, wx[129], p.y);
            p.z = fmaf(x2, wx[130], p.z); p.w = fmaf(x2, wx[131], p.w);
            p.x = fmaf(x3, wx[192], p.x); p.y = fmaf(x3, wx[193], p.y);
            p.z = fmaf(x3, wx[194], p.z); p.w = fmaf(x3, wx[195], p.w);
            p.x = fmaf(x4, wx[256], p.x); p.y = fmaf(x4, wx[257], p.y);
            p.z = fmaf(x4, wx[258], p.z); p.w = fmaf(x4, wx[259], p.w);
            float cn = sigf(p.y) * creg[nb] + sigf(p.x) * tanha(p.z);
            float h = sigf(p.w) * tanha(cn);
            creg[nb] = cn;
            __nv_bfloat16 hb = __float2bfloat16_rn(h);
            __nv_bfloat16 lb = __float2bfloat16_rn(h - __bfloat162float(hb));
            u32 hl = (u32)*(u16*)&hb | ((u32)*(u16*)&lb << 16);
            u32 pr = __shfl_xor_sync(0xffffffffu, hl, 2);
            hiw[nb] = (hl & 0xFFFFu) | ((pr & 0xFFFFu) << 16);
            low[nb] = (hl >> 16) | (pr & 0xFFFF0000u);
        }
        if (upart == 0) {
            size_t base = (size_t)(b0 + myrow) * 256 + ut * 8 + 4 * nhalf;
            uint4 hv = make_uint4(hiw[0], hiw[1], hiw[2], hiw[3]);
            uint4 lv = make_uint4(low[0], low[1], low[2], low[3]);
            __stcg((uint4*)&hiOut[base], hv);
            __stcg((uint4*)&loOut[base], lv);
            size_t hb2 = ((size_t)t * Bn + b0 + myrow) * 256 + ut * 8 + 4 * nhalf;
            __stcg((uint4*)&g_hsH[hb2], hv);
            __stcg((uint4*)&g_hsL[hb2], lv);
        }
        __syncwarp();
        if (lane == 0 && t < Tn - 1) red_rel(ctr);
    }
    if (tid == 0) {
        int old = atomicAdd(done, 1);
        if (old == 31) { atomicExch(ctr, 0); atomicExch(done, 0); }
    }
}

// =================== latent stages ==========================================
__global__ void latent1(const float* __restrict__ W, const float* __restrict__ bias,
                        const float* __restrict__ eps,
                        float* __restrict__ zm, float* __restrict__ zl)
{
    int b = blockIdx.x, j = threadIdx.x;
    const __nv_bfloat16* fh = (const __nv_bfloat16*)g_hfH[0];
    const __nv_bfloat16* fl = (const __nv_bfloat16*)g_hfL[0];
    const __nv_bfloat16* bh = (const __nv_bfloat16*)g_hbH[0];
    const __nv_bfloat16* bl = (const __nv_bfloat16*)g_hbL[0];
    float sm = bias[j], sl = bias[j + Zn];
    for (int k = 0; k < Hn; k++) {
        float a = __bfloat162float(fh[b * Hn + k]) + __bfloat162float(fl[b * Hn + k]);
        sm = fmaf(a, W[k * (2 * Zn) + j], sm);
        sl = fmaf(a, W[k * (2 * Zn) + Zn + j], sl);
    }
    for (int k = 0; k < Hn; k++) {
        float a = __bfloat162float(bh[b * Hn + k]) + __bfloat162float(bl[b * Hn + k]);
        sm = fmaf(a, W[(Hn + k) * (2 * Zn) + j], sm);
        sl = fmaf(a, W[(Hn + k) * (2 * Zn) + Zn + j], sl);
    }
    zm[b * Zn + j] = sm;
    zl[b * Zn + j] = sl;
    g_z[b * Zn + j] = sm + expf(0.5f * sl) * eps[b * Zn + j];
}

__global__ __launch_bounds__(256) void latent2(
    const float* __restrict__ init_W, const float* __restrict__ init_b,
    const float* __restrict__ dec_Wx, const float* __restrict__ dec_b)
{
    __shared__ float zs[32][Zn];
    const int tid = threadIdx.x;
    const int tx = tid & 31, ty = tid >> 5;
    const int b0 = blockIdx.x * 32;
    const int col0 = blockIdx.y * 128;
    const bool isInit = (col0 < 2 * Dn);

    for (int i = tid; i < 32 * Zn; i += 256)
        zs[i >> 7][i & 127] = g_z[(b0 + (i >> 7)) * Zn + (i & 127)];
    __syncthreads();

    const int col = col0 + tx * 4;
    const float* Wcol = isInit ? (init_W + col) : (dec_Wx + 5 * (4 * Dn) + (col - 2 * Dn));
    const int wstride = isInit ? (2 * Dn) : (4 * Dn);

    float acc[4][4] = {};
    #pragma unroll 4
    for (int k = 0; k < Zn; k++) {
        float4 w = *(const float4*)&Wcol[k * wstride];
        float a0 = zs[ty * 4 + 0][k], a1 = zs[ty * 4 + 1][k];
        float a2 = zs[ty * 4 + 2][k], a3 = zs[ty * 4 + 3][k];
        acc[0][0] = fmaf(a0, w.x, acc[0][0]); acc[0][1] = fmaf(a0, w.y, acc[0][1]);
        acc[0][2] = fmaf(a0, w.z, acc[0][2]); acc[0][3] = fmaf(a0, w.w, acc[0][3]);
        acc[1][0] = fmaf(a1, w.x, acc[1][0]); acc[1][1] = fmaf(a1, w.y, acc[1][1]);
        acc[1][2] = fmaf(a1, w.z, acc[1][2]); acc[1][3] = fmaf(a1, w.w, acc[1][3]);
        acc[2][0] = fmaf(a2, w.x, acc[2][0]); acc[2][1] = fmaf(a2, w.y, acc[2][1]);
        acc[2][2] = fmaf(a2, w.z, acc[2][2]); acc[2][3] = fmaf(a2, w.w, acc[2][3]);
        acc[3][0] = fmaf(a3, w.x, acc[3][0]); acc[3][1] = fmaf(a3, w.y, acc[3][1]);
        acc[3][2] = fmaf(a3, w.z, acc[3][2]); acc[3][3] = fmaf(a3, w.w, acc[3][3]);
    }

    __nv_bfloat16* hH = (__nv_bfloat16*)g_hdH[0];
    __nv_bfloat16* hL = (__nv_bfloat16*)g_hdL[0];
    #pragma unroll
    for (int r = 0; r < 4; r++) {
        int b = b0 + ty * 4 + r;
        #pragma unroll
        for (int c = 0; c < 4; c++) {
            int cc = col + c;
            if (isInit) {
                float v = tanhf(acc[r][c] + init_b[cc]);
                if (cc < Dn) {
                    __nv_bfloat16 hb = __float2bfloat16_rn(v);
                    hH[(size_t)b * Dn + cc] = hb;
                    hL[(size_t)b * Dn + cc] = __float2bfloat16_rn(v - __bfloat162float(hb));
                } else {
                    g_cdT[(size_t)(cc - Dn) * Bn + b] = v;
                }
            } else {
                int c2 = cc - 2 * Dn;
                g_zgT[(size_t)c2 * Bn + b] = acc[r][c] + dec_b[c2];
            }
        }
    }
}

// =================== mix weight prepack =====================================
__global__ void pack_mix(const float* __restrict__ Wm) {
    int i = blockIdx.x * 256 + threadIdx.x;
    int kp = i >> 7, c = i & 127;
    float w0 = (c < Pn) ? __ldg(&Wm[(2 * kp)     * Pn + c]) : 0.f;
    float w1 = (c < Pn) ? __ldg(&Wm[(2 * kp + 1) * Pn + c]) : 0.f;
    u32 lo, hi = pack_hi(w0, w1, lo);
    g_WmH[kp * 128 + c] = hi;
    g_WmL[kp * 128 + c] = lo;
}

// =================== output head: tensor-core GEMM, prepacked W =============
#define MIX_SMEM 201728
__global__ __launch_bounds__(256) void mix_mma(
    const float* __restrict__ bm, float* __restrict__ out)
{
    extern __shared__ u32 sm[];
    u32*  Whi = sm;
    u32*  Wlo = sm + 18432;
    u32*  Ab  = sm + 36864;
    float* Csm = (float*)(sm + 46080);

    const int tid = threadIdx.x, lane = tid & 31, warp = tid >> 5;
    const int g = lane >> 2, t4 = lane & 3;
    const int m0 = (warp & 3) * 16, n0 = (warp >> 2) * 32;
    const int row0 = blockIdx.x * 64;
    const int col0 = blockIdx.y * 64;

    for (int i = tid; i < 16384; i += 256) {
        int kp = i >> 6, c = i & 63;
        Whi[kp * WP + c] = g_WmH[kp * 128 + col0 + c];
        Wlo[kp * WP + c] = g_WmL[kp * 128 + col0 + c];
    }
    __syncthreads();

    const int srow = ((warp & 3) << 4) + ((warp >> 2) << 3) + (lane >> 2);
    const int sw = lane & 3;
    const int ra0 = (m0 + g) * AP + t4, ra1 = (m0 + g + 8) * AP + t4;
    float acc[4][4] = {};
    mma_steps<8>(acc, &g_hsH[(size_t)(row0 + srow) * 256], &g_hsL[(size_t)(row0 + srow) * 256],
                 Ab, Whi, Wlo, srow, sw, ra0, ra1, n0, g, t4);

    #pragma unroll
    for (int nb = 0; nb < 4; nb++) {
        int colp = n0 + 8 * nb + 2 * t4;
        *(float2*)&Csm[(m0 + g) * 68 + colp]     = make_float2(acc[nb][0], acc[nb][1]);
        *(float2*)&Csm[(m0 + g + 8) * 68 + colp] = make_float2(acc[nb][2], acc[nb][3]);
    }
    __syncthreads();

    if (tid < 64) {
        int grow = row0 + tid;
        int tt = grow >> 8, bb2 = grow & 255;
        float* o = out + ((size_t)bb2 * Tn + tt) * Pn;
        const float* yr = &Csm[tid * 68];
        if (col0 == 0) {
            float e[Kn]; float m = -1e30f;
            #pragma unroll
            for (int j = 0; j < Kn; j++) { e[j] = yr[j] + __ldg(&bm[j]); m = fmaxf(m, e[j]); }
            float s = 0.f;
            #pragma unroll
            for (int j = 0; j < Kn; j++) { e[j] = expf(e[j] - m); s += e[j]; }
            float inv = 1.0f / s;
            #pragma unroll
            for (int j = 0; j < Kn; j++) o[j] = e[j] * inv;
            for (int c = 20; c < 60; c++) o[c] = yr[c] + __ldg(&bm[c]);
            for (int c = 60; c < 64; c++) o[c] = expf(yr[c] + __ldg(&bm[c]));
        } else {
            for (int c = 0; c < 59; c++) {
                int col = 64 + c;
                float v = yr[c] + __ldg(&bm[col]);
                if (col < 100)      v = expf(v);
                else if (col < 120) v = tanhf(v);
                o[col] = v;
            }
        }
    }
}

// =================== launcher ================================================
extern "C" void kernel_launch(void* const* d_in, const int* in_sizes, int n_in,
                              void* d_out, int out_size)
{
    (void)in_sizes; (void)n_in; (void)out_size;
    const float* data      = (const float*)d_in[0];
    const float* eps       = (const float*)d_in[1];
    const float* enc_Wx_f  = (const float*)d_in[2];
    const float* enc_Wh_f  = (const float*)d_in[3];
    const float* enc_b_f   = (const float*)d_in[4];
    const float* enc_Wx_b  = (const float*)d_in[5];
    const float* enc_Wh_b  = (const float*)d_in[6];
    const float* enc_b_b   = (const float*)d_in[7];
    const float* enc_out_W = (const float*)d_in[8];
    const float* enc_out_b = (const float*)d_in[9];
    const float* init_W    = (const float*)d_in[10];
    const float* init_b    = (const float*)d_in[11];
    const float* dec_Wx    = (const float*)d_in[12];
    const float* dec_Wh    = (const float*)d_in[13];
    const float* dec_b     = (const float*)d_in[14];
    const float* mix_W     = (const float*)d_in[15];
    const float* mix_b     = (const float*)d_in[16];
    float* out = (float*)d_out;

    cudaFuncSetAttribute(enc_persist, cudaFuncAttributeMaxDynamicSharedMemorySize, ENC_SMEM);
    cudaFuncSetAttribute(dec_persist, cudaFuncAttributeMaxDynamicSharedMemorySize, DEC_SMEM);
    cudaFuncSetAttribute(mix_mma,     cudaFuncAttributeMaxDynamicSharedMemorySize, MIX_SMEM);

    const size_t params_sz = (size_t)Bn * Tn * Pn;

    pack_mix<<<128, 256>>>(mix_W);
    enc_persist<<<128, 256, ENC_SMEM>>>(data, enc_Wx_f, enc_Wh_f, enc_b_f,
                                        enc_Wx_b, enc_Wh_b, enc_b_b);
    latent1<<<Bn, 128>>>(enc_out_W, enc_out_b, eps,
                         out + params_sz, out + params_sz + (size_t)Bn * Zn);
    latent2<<<dim3(8, 24), 256>>>(init_W, init_b, dec_Wx, dec_b);
    dec_persist<<<128, 256, DEC_SMEM>>>(data, dec_Wx, dec_Wh);
    mix_mma<<<dim3(TB / 64, 2), 256, MIX_SMEM>>>(mix_b, out);
}